// round 13
// baseline (speedup 1.0000x reference)
#include <cuda_runtime.h>
#include <cuda_bf16.h>
#include <math.h>
#include <stdint.h>

// Problem constants
#define Nn 100000
#define Ee 600000
#define IN_DIM 64
#define Hd 128
#define Ld 3
#define Gg 256
#define Cc 10
#define NTILES ((Nn + 127) / 128)

// ---------------- device scratch ----------------
__device__ float  g_h[(size_t)Nn * Hd];
__device__ float  g_q[(size_t)Nn * Hd];
__device__ float  g_s[(size_t)Nn * Hd];
__device__ __align__(16) __nv_bfloat16 g_kv[(size_t)Nn * 256]; // k|v bf16
__device__ double g_sum[Hd];
__device__ double g_sumsq[Hd];
__device__ float  g_scale[Hd];
__device__ float  g_shift[Hd];
__device__ float  g_pool[Gg * Hd];
__device__ float  g_cnt[Gg];
__device__ int    g_ctr;
// CSR
__device__ int    g_deg[Nn];
__device__ int    g_off[Nn + 1];
__device__ int    g_srcSorted[Ee];
// bf16 hi/lo split staging (layer-1 A image + current-layer B)
__device__ __align__(16) __nv_bfloat16 g_Ahi[(size_t)NTILES * 128 * IN_DIM];
__device__ __align__(16) __nv_bfloat16 g_Alo[(size_t)NTILES * 128 * IN_DIM];
__device__ __align__(16) __nv_bfloat16 g_Bhi[512 * 128];
__device__ __align__(16) __nv_bfloat16 g_Blo[512 * 128];
__device__ float  g_bias[512];

// ---------------- asm helpers ----------------
__device__ __forceinline__ uint32_t smem_u32(const void* p) {
    uint32_t a;
    asm("{ .reg .u64 t; cvta.to.shared.u64 t, %1; cvt.u32.u64 %0, t; }" : "=r"(a) : "l"(p));
    return a;
}

__device__ __forceinline__ void mma16816(float* d,
    uint32_t a0, uint32_t a1, uint32_t a2, uint32_t a3,
    uint32_t b0, uint32_t b1)
{
    asm volatile(
        "mma.sync.aligned.m16n8k16.row.col.f32.bf16.bf16.f32 "
        "{%0,%1,%2,%3}, {%4,%5,%6,%7}, {%8,%9}, {%0,%1,%2,%3};"
        : "+f"(d[0]), "+f"(d[1]), "+f"(d[2]), "+f"(d[3])
        : "r"(a0), "r"(a1), "r"(a2), "r"(a3), "r"(b0), "r"(b1));
}

__device__ __forceinline__ void ldsm4(uint32_t* r, uint32_t addr) {
    asm volatile("ldmatrix.sync.aligned.m8n8.x4.shared.b16 {%0,%1,%2,%3}, [%4];"
        : "=r"(r[0]), "=r"(r[1]), "=r"(r[2]), "=r"(r[3]) : "r"(addr));
}

#define CP_ASYNC16(dst, src) \
    asm volatile("cp.async.cg.shared.global [%0], [%1], 16;" :: "r"(dst), "l"(src))
#define CP_COMMIT()  asm volatile("cp.async.commit_group;" ::: "memory")

__device__ __forceinline__ float4 ld_bf4(const __nv_bfloat16* p) {
    uint2 u = *(const uint2*)p;
    __nv_bfloat162 a = *reinterpret_cast<__nv_bfloat162*>(&u.x);
    __nv_bfloat162 b = *reinterpret_cast<__nv_bfloat162*>(&u.y);
    float2 fa = __bfloat1622float2(a), fb = __bfloat1622float2(b);
    return make_float4(fa.x, fa.y, fb.x, fb.y);
}

// ---------------- fused layer-1 prep (+ deg zero) ----------------
__global__ void prep_layer1(const float* __restrict__ x, int n, int ntiles,
                            const float* __restrict__ Wq, const float* __restrict__ Wk,
                            const float* __restrict__ Wv, const float* __restrict__ Ws,
                            const float* __restrict__ bq, const float* __restrict__ bk,
                            const float* __restrict__ bv, const float* __restrict__ bs)
{
    long aTot = (long)ntiles * 128 * IN_DIM;
    long bTot = 512 * IN_DIM;
    long total = aTot + bTot + 512 + n;
    long stride = (long)gridDim.x * blockDim.x;
    for (long idx = (long)blockIdx.x * blockDim.x + threadIdx.x; idx < total; idx += stride) {
        if (idx < aTot) {
            long row = idx / IN_DIM;
            int  k = (int)(idx % IN_DIM);
            float v = (row < n) ? x[row * IN_DIM + k] : 0.f;
            __nv_bfloat16 hi = __float2bfloat16(v);
            g_Ahi[idx] = hi;
            g_Alo[idx] = __float2bfloat16(v - __bfloat162float(hi));
        } else if (idx < aTot + bTot) {
            int j = (int)(idx - aTot);
            int nglob = j / IN_DIM, k = j % IN_DIM;
            int w = nglob >> 7, nloc = nglob & 127;
            const float* W = (w == 0) ? Wq : (w == 1) ? Wk : (w == 2) ? Wv : Ws;
            float v = W[(size_t)k * Hd + nloc];
            __nv_bfloat16 hi = __float2bfloat16(v);
            g_Bhi[j] = hi;
            g_Blo[j] = __float2bfloat16(v - __bfloat162float(hi));
        } else if (idx < aTot + bTot + 512) {
            int nglob = (int)(idx - aTot - bTot);
            int w = nglob >> 7, nloc = nglob & 127;
            const float* B = (w == 0) ? bq : (w == 1) ? bk : (w == 2) ? bv : bs;
            g_bias[nglob] = B[nloc];
        } else {
            g_deg[idx - aTot - bTot - 512] = 0;
        }
    }
}

// ---------------- setup2 ----------------
__global__ void setup2(const int* __restrict__ dst, const int* __restrict__ batch,
                       int n, int E) {
    int idx = blockIdx.x * blockDim.x + threadIdx.x;
    if (idx < E) atomicAdd(&g_deg[dst[idx]], 1);
    if (idx == 0) { g_off[0] = 0; g_ctr = 0; }
    if (idx < Hd) { g_sum[idx] = 0.0; g_sumsq[idx] = 0.0; }
    if (idx < Gg * Hd) g_pool[idx] = 0.f;
    if (idx < Gg) {
        int g = idx;
        int lo = 0, hi = n;
        while (lo < hi) { int mid = (lo + hi) >> 1; if (batch[mid] < g) lo = mid + 1; else hi = mid; }
        int lb = lo;
        lo = 0; hi = n;
        while (lo < hi) { int mid = (lo + hi) >> 1; if (batch[mid] <= g) lo = mid + 1; else hi = mid; }
        g_cnt[g] = (float)(lo - lb);
    }
}

__global__ void __launch_bounds__(1024) scan_block(int n) {
    __shared__ int sh[1024];
    int t = threadIdx.x;
    int chunk = (n + 1023) >> 10;
    int s0 = min(t * chunk, n), s1 = min(s0 + chunk, n);
    int s = 0;
    for (int i = s0; i < s1; i++) s += g_deg[i];
    sh[t] = s;
    __syncthreads();
    #pragma unroll
    for (int d = 1; d < 1024; d <<= 1) {
        int v = (t >= d) ? sh[t - d] : 0;
        __syncthreads();
        sh[t] += v;
        __syncthreads();
    }
    int run = (t == 0) ? 0 : sh[t - 1];
    for (int i = s0; i < s1; i++) {
        int d = g_deg[i];
        g_deg[i] = run;
        run += d;
        g_off[i + 1] = run;
    }
}

// ---------------- GEMM + scatter slice ----------------
#define BSTR 40
#define BTSZ (128 * BSTR)

template<int K, int S, bool FUSE>
__global__ void __launch_bounds__(256, 2) gemm_mma(int n,
        const int* __restrict__ esrc, const int* __restrict__ edst, int E) {
    if (blockIdx.y == 2) {
        int chunk = (E + gridDim.x - 1) / gridDim.x;
        int e0 = blockIdx.x * chunk;
        int e1 = min(e0 + chunk, E);
        for (int e = e0 + threadIdx.x; e < e1; e += 256) {
            int pos = atomicAdd(&g_deg[edst[e]], 1);
            g_srcSorted[pos] = esrc[e];
        }
        return;
    }

    constexpr int ASTR = K + 8;
    constexpr int ATSZ = 128 * ASTR;
    constexpr int NK = K / 32;
    constexpr int P = 2 * NK;
    extern __shared__ __nv_bfloat16 sm[];
    const int B_OFF = 2 * ATSZ;

    const int tid = threadIdx.x;
    const int tile = blockIdx.x;
    const int cb = blockIdx.y * 2;
    const int wid = tid >> 5, lane = tid & 31;
    const int wm = (wid & 3) * 32, wn = (wid >> 2) * 64;
    const int gid = lane >> 2, tig = lane & 3;
    const uint32_t smb = smem_u32(sm);

    auto stageB = [&](int pp) {
        int buf = pp % S;
        int cc = cb + pp / NK;
        int kt = (pp % NK) * 32;
        #pragma unroll
        for (int t = 0; t < 4; t++) {
            int idx = tid + t * 256;
            int img = idx >> 9, rem = idx & 511;
            int r = rem >> 2, c = rem & 3;
            const __nv_bfloat16* sp = (img ? g_Blo : g_Bhi) + (size_t)(cc * 128 + r) * K + kt + c * 8;
            uint32_t d = smb + (uint32_t)(B_OFF + buf * 2 * BTSZ + img * BTSZ + r * BSTR + c * 8) * 2;
            CP_ASYNC16(d, sp);
        }
        CP_COMMIT();
    };

    if (FUSE) {
        #pragma unroll
        for (int s = 0; s < S - 1; s++) stageB(s);
        const int cg = (tid & 31) * 4;
        const float4 sc4 = *(const float4*)(g_scale + cg);
        const float4 sh4 = *(const float4*)(g_shift + cg);
        #pragma unroll
        for (int t = 0; t < 16; t++) {
            int idx = tid + t * 256;
            int r = idx >> 5;
            long grow = (long)tile * 128 + r;
            float4 v = make_float4(0.f, 0.f, 0.f, 0.f);
            if (grow < n) v = *(const float4*)(g_h + grow * 128 + cg);
            v.x = fmaxf(v.x * sc4.x + sh4.x, 0.f);
            v.y = fmaxf(v.y * sc4.y + sh4.y, 0.f);
            v.z = fmaxf(v.z * sc4.z + sh4.z, 0.f);
            v.w = fmaxf(v.w * sc4.w + sh4.w, 0.f);
            __nv_bfloat162 h0 = __floats2bfloat162_rn(v.x, v.y);
            __nv_bfloat162 h1 = __floats2bfloat162_rn(v.z, v.w);
            float2 f0 = __bfloat1622float2(h0), f1 = __bfloat1622float2(h1);
            __nv_bfloat162 l0 = __floats2bfloat162_rn(v.x - f0.x, v.y - f0.y);
            __nv_bfloat162 l1 = __floats2bfloat162_rn(v.z - f1.x, v.w - f1.y);
            uint2 uh, ul;
            uh.x = *(uint32_t*)&h0; uh.y = *(uint32_t*)&h1;
            ul.x = *(uint32_t*)&l0; ul.y = *(uint32_t*)&l1;
            *(uint2*)&sm[r * ASTR + cg] = uh;
            *(uint2*)&sm[ATSZ + r * ASTR + cg] = ul;
        }
    } else {
        const __nv_bfloat16* aH = g_Ahi + (size_t)tile * 128 * K;
        const __nv_bfloat16* aL = g_Alo + (size_t)tile * 128 * K;
        constexpr int ACH = 2 * 128 * (K / 8);
        #pragma unroll
        for (int t = 0; t < ACH / 256; t++) {
            int i = tid + t * 256;
            int img = i / (128 * (K / 8));
            int rem = i % (128 * (K / 8));
            int r = rem / (K / 8), c = rem % (K / 8);
            const __nv_bfloat16* sp = (img ? aL : aH) + (size_t)r * K + c * 8;
            uint32_t d = smb + (uint32_t)(img * ATSZ + r * ASTR + c * 8) * 2;
            CP_ASYNC16(d, sp);
        }
        #pragma unroll
        for (int s = 0; s < S - 1; s++) stageB(s);
    }

    float acc[2][8][4] = {};

    #pragma unroll 1
    for (int p = 0; p < P; p++) {
        if (p + S - 1 < P) {
            stageB(p + S - 1);
            asm volatile("cp.async.wait_group %0;" :: "n"(S - 1) : "memory");
        } else {
            asm volatile("cp.async.wait_group 0;" ::: "memory");
        }
        __syncthreads();

        const int ktA = (p % NK) * 32;
        const uint32_t bbase = smb + (uint32_t)(B_OFF + (p % S) * 2 * BTSZ) * 2;

        #pragma unroll
        for (int ks = 0; ks < 2; ks++) {
            const int kb = ks * 16;
            uint32_t ah[2][4], al[2][4];
            #pragma unroll
            for (int mt = 0; mt < 2; mt++) {
                int row = wm + mt * 16 + (lane & 15);
                int col = ktA + kb + ((lane & 16) ? 8 : 0);
                uint32_t ad = smb + (uint32_t)(row * ASTR + col) * 2;
                ldsm4(ah[mt], ad);
                ldsm4(al[mt], ad + ATSZ * 2);
            }
            #pragma unroll
            for (int ntp = 0; ntp < 4; ntp++) {
                int row = wn + ntp * 16 + (lane & 7) + ((lane & 16) ? 8 : 0);
                int col = kb + ((lane & 8) ? 8 : 0);
                uint32_t bd = bbase + (uint32_t)(row * BSTR + col) * 2;
                uint32_t bh[4], bl[4];
                ldsm4(bh, bd);
                ldsm4(bl, bd + BTSZ * 2);
                #pragma unroll
                for (int sub = 0; sub < 2; sub++) {
                    int nt = ntp * 2 + sub;
                    #pragma unroll
                    for (int mt = 0; mt < 2; mt++) {
                        mma16816(acc[mt][nt], ah[mt][0], ah[mt][1], ah[mt][2], ah[mt][3], bh[sub*2], bh[sub*2+1]);
                        mma16816(acc[mt][nt], ah[mt][0], ah[mt][1], ah[mt][2], ah[mt][3], bl[sub*2], bl[sub*2+1]);
                        mma16816(acc[mt][nt], al[mt][0], al[mt][1], al[mt][2], al[mt][3], bh[sub*2], bh[sub*2+1]);
                    }
                }
            }
        }
        __syncthreads();

        if ((p % NK) == NK - 1) {
            const int cc = cb + p / NK;
            #pragma unroll
            for (int mt = 0; mt < 2; mt++) {
                long r0 = (long)tile * 128 + wm + mt * 16 + gid;
                #pragma unroll
                for (int nt = 0; nt < 8; nt++) {
                    int col = wn + nt * 8 + tig * 2;
                    float b0 = g_bias[cc * 128 + col], b1 = g_bias[cc * 128 + col + 1];
                    float v0 = acc[mt][nt][0] + b0, v1 = acc[mt][nt][1] + b1;
                    float v2 = acc[mt][nt][2] + b0, v3 = acc[mt][nt][3] + b1;
                    if (cc == 0) {
                        if (r0 < n)     *(float2*)(g_q + r0 * 128 + col)       = make_float2(v0, v1);
                        if (r0 + 8 < n) *(float2*)(g_q + (r0 + 8) * 128 + col) = make_float2(v2, v3);
                    } else if (cc == 3) {
                        if (r0 < n)     *(float2*)(g_s + r0 * 128 + col)       = make_float2(v0, v1);
                        if (r0 + 8 < n) *(float2*)(g_s + (r0 + 8) * 128 + col) = make_float2(v2, v3);
                    } else {
                        int off = (cc == 2) ? 128 : 0;
                        __nv_bfloat162 p0 = __floats2bfloat162_rn(v0, v1);
                        __nv_bfloat162 p1 = __floats2bfloat162_rn(v2, v3);
                        if (r0 < n)     *(__nv_bfloat162*)(g_kv + r0 * 256 + off + col)       = p0;
                        if (r0 + 8 < n) *(__nv_bfloat162*)(g_kv + (r0 + 8) * 256 + off + col) = p1;
                    }
                    acc[mt][nt][0] = 0.f; acc[mt][nt][1] = 0.f;
                    acc[mt][nt][2] = 0.f; acc[mt][nt][3] = 0.f;
                }
            }
        }
    }
}

// ---------------- fused attention (exact R8) + BN stats + next-layer B prep ----------------
__global__ void __launch_bounds__(256, 6) attn_fused(int n, int NB,
        const float* __restrict__ gamma, const float* __restrict__ beta,
        const float* __restrict__ Wq, const float* __restrict__ Wk,
        const float* __restrict__ Wv, const float* __restrict__ Ws,
        const float* __restrict__ bq, const float* __restrict__ bk,
        const float* __restrict__ bv, const float* __restrict__ bs) {
    if ((int)blockIdx.x >= NB) {
        if (Wq) {
            int idx = ((int)blockIdx.x - NB) * 256 + threadIdx.x;
            int nglob = idx / Hd, k = idx % Hd;
            int w = nglob >> 7, nloc = nglob & 127;
            const float* W = (w == 0) ? Wq : (w == 1) ? Wk : (w == 2) ? Wv : Ws;
            float v = W[(size_t)k * Hd + nloc];
            __nv_bfloat16 hi = __float2bfloat16(v);
            g_Bhi[idx] = hi;
            g_Blo[idx] = __float2bfloat16(v - __bfloat162float(hi));
            if (k == 0) {
                const float* B = (w == 0) ? bq : (w == 1) ? bk : (w == 2) ? bv : bs;
                g_bias[nglob] = B[nloc];
            }
        }
        return;
    }

    __shared__ float ssum[Hd], ssq[Hd];
    __shared__ int sh_last;
    for (int i = threadIdx.x; i < Hd; i += 256) { ssum[i] = 0.f; ssq[i] = 0.f; }
    __syncthreads();

    const int lane = threadIdx.x & 31;
    const int c0 = lane * 4;
    const int wstride = NB * 8;
    float ls0 = 0.f, ls1 = 0.f, ls2 = 0.f, ls3 = 0.f;
    float lq0 = 0.f, lq1 = 0.f, lq2 = 0.f, lq3 = 0.f;

    for (int node = blockIdx.x * 8 + (threadIdx.x >> 5); node < n; node += wstride) {
        const int off0 = g_off[node];
        const int deg  = g_off[node + 1] - off0;
        const float4 q = *(const float4*)(g_q + (size_t)node * 128 + c0);

        float m_run = -INFINITY, sum_run = 0.f;
        float ax = 0.f, ay = 0.f, az = 0.f, aw = 0.f;

        for (int base = 0; base < deg; base += 32) {
            const int c = min(32, deg - base);
            int myidx = (lane < c) ? g_srcSorted[off0 + base + lane] : 0;

            float myscore = -INFINITY;
            #pragma unroll 4
            for (int j = 0; j < c; j++) {
                int s = __shfl_sync(0xffffffffu, myidx, j);
                float4 kk = ld_bf4(g_kv + (size_t)s * 256 + c0);
                float p = q.x * kk.x + q.y * kk.y + q.z * kk.z + q.w * kk.w;
                #pragma unroll
                for (int o = 16; o; o >>= 1) p += __shfl_xor_sync(0xffffffffu, p, o);
                if (lane == j) myscore = p;
            }
            float sc = myscore * 0.08838834764831845f;

            float cm = sc;
            #pragma unroll
            for (int o = 16; o; o >>= 1) cm = fmaxf(cm, __shfl_xor_sync(0xffffffffu, cm, o));
            float m_new = fmaxf(m_run, cm);
            float resc = expf(m_run - m_new);
            float w_l = (lane < c) ? expf(sc - m_new) : 0.f;
            float csum = w_l;
            #pragma unroll
            for (int o = 16; o; o >>= 1) csum += __shfl_xor_sync(0xffffffffu, csum, o);
            sum_run = sum_run * resc + csum;
            ax *= resc; ay *= resc; az *= resc; aw *= resc;
            m_run = m_new;

            #pragma unroll 4
            for (int j = 0; j < c; j++) {
                int s = __shfl_sync(0xffffffffu, myidx, j);
                float wj = __shfl_sync(0xffffffffu, w_l, j);
                float4 vv = ld_bf4(g_kv + (size_t)s * 256 + 128 + c0);
                ax += wj * vv.x;
                ay += wj * vv.y;
                az += wj * vv.z;
                aw += wj * vv.w;
            }
        }

        float inv = (deg > 0) ? 1.f / sum_run : 0.f;
        float4 sk = *(const float4*)(g_s + (size_t)node * 128 + c0);
        float h0 = ax * inv + sk.x;
        float h1 = ay * inv + sk.y;
        float h2 = az * inv + sk.z;
        float h3 = aw * inv + sk.w;
        *(float4*)(g_h + (size_t)node * Hd + c0) = make_float4(h0, h1, h2, h3);
        ls0 += h0; ls1 += h1; ls2 += h2; ls3 += h3;
        lq0 += h0 * h0; lq1 += h1 * h1; lq2 += h2 * h2; lq3 += h3 * h3;
    }

    atomicAdd(&ssum[c0 + 0], ls0); atomicAdd(&ssq[c0 + 0], lq0);
    atomicAdd(&ssum[c0 + 1], ls1); atomicAdd(&ssq[c0 + 1], lq1);
    atomicAdd(&ssum[c0 + 2], ls2); atomicAdd(&ssq[c0 + 2], lq2);
    atomicAdd(&ssum[c0 + 3], ls3); atomicAdd(&ssq[c0 + 3], lq3);
    __syncthreads();
    if (threadIdx.x < Hd) {
        atomicAdd(&g_sum[threadIdx.x], (double)ssum[threadIdx.x]);
        atomicAdd(&g_sumsq[threadIdx.x], (double)ssq[threadIdx.x]);
    }

    __threadfence();
    if (threadIdx.x == 0) {
        int t = atomicAdd(&g_ctr, 1);
        sh_last = (t == NB - 1);
    }
    __syncthreads();
    if (sh_last) {
        int ch = threadIdx.x;
        if (ch < Hd) {
            double mean = g_sum[ch] / n;
            double var  = g_sumsq[ch] / n - mean * mean;
            if (var < 0.0) var = 0.0;
            float invs = (float)rsqrt(var + 1e-5);
            float scv = invs * gamma[ch];
            g_scale[ch] = scv;
            g_shift[ch] = beta[ch] - (float)mean * scv;
            g_sum[ch] = 0.0;
            g_sumsq[ch] = 0.0;
        }
        if (threadIdx.x == 0) g_ctr = 0;
    }
}

// ---------------- last-layer BN apply + pool ----------------
__global__ void bn_pool(int n, const int* __restrict__ batch) {
    long stride = (long)gridDim.x * blockDim.x;
    long total = (long)n * Hd;
    for (long i = (long)blockIdx.x * blockDim.x + threadIdx.x; i < total; i += stride) {
        int c = (int)(i & 127);
        float v = fmaxf(g_h[i] * g_scale[c] + g_shift[c], 0.f);
        int node = (int)(i >> 7);
        atomicAdd(&g_pool[batch[node] * Hd + c], v);
    }
}

__global__ void classify(const float* __restrict__ W, const float* __restrict__ b,
                         float* __restrict__ out) {
    int g = blockIdx.x;
    int c = threadIdx.x;
    if (c >= Cc) return;
    float inv = 1.f / fmaxf(g_cnt[g], 1.f);
    float acc = 0.f;
    #pragma unroll 8
    for (int h = 0; h < Hd; h++) acc += g_pool[g * Hd + h] * W[h * Cc + c];
    out[g * Cc + c] = acc * inv + b[c];
}

// ---------------- host orchestration ----------------
extern "C" void kernel_launch(void* const* d_in, const int* in_sizes, int n_in,
                              void* d_out, int out_size)
{
    const float* x     = (const float*)d_in[0];
    const int*   ei    = (const int*)d_in[1];
    const int*   batch = (const int*)d_in[2];
    const float* Wq1 = (const float*)d_in[3];
    const float* bq1 = (const float*)d_in[4];
    const float* Wk1 = (const float*)d_in[5];
    const float* bk1 = (const float*)d_in[6];
    const float* Wv1 = (const float*)d_in[7];
    const float* bv1 = (const float*)d_in[8];
    const float* Ws1 = (const float*)d_in[9];
    const float* bs1 = (const float*)d_in[10];
    const float* bn1g = (const float*)d_in[11];
    const float* bn1b = (const float*)d_in[12];
    const float* Wq = (const float*)d_in[13];
    const float* bq = (const float*)d_in[14];
    const float* Wk = (const float*)d_in[15];
    const float* bk = (const float*)d_in[16];
    const float* Wv = (const float*)d_in[17];
    const float* bv = (const float*)d_in[18];
    const float* Ws = (const float*)d_in[19];
    const float* bs = (const float*)d_in[20];
    const float* bng = (const float*)d_in[21];
    const float* bnb = (const float*)d_in[22];
    const float* linW = (const float*)d_in[23];
    const float* linb = (const float*)d_in[24];

    int n = in_sizes[0] / IN_DIM;
    int E = in_sizes[1] / 2;
    int ntiles = (n + 127) / 128;
    const int* src = ei;
    const int* dst = ei + E;
    const int NB = 2048;

    const int SMEM64  = (2 * 128 * (IN_DIM + 8)) * 2 + 3 * 2 * BTSZ * 2;  // 98304
    const int SMEM128 = (2 * 128 * (Hd + 8)) * 2 + 2 * 2 * BTSZ * 2;      // 110592
    cudaFuncSetAttribute((const void*)gemm_mma<IN_DIM, 3, false>, cudaFuncAttributeMaxDynamicSharedMemorySize, SMEM64);
    cudaFuncSetAttribute((const void*)gemm_mma<Hd, 2, true>,      cudaFuncAttributeMaxDynamicSharedMemorySize, SMEM128);

    // #1 prep (A image + B/bias + deg zero), #2 setup (count + zeros + counts), #3 scan
    prep_layer1<<<1024, 256>>>(x, n, ntiles, Wq1, Wk1, Wv1, Ws1, bq1, bk1, bv1, bs1);
    setup2<<<(E + 255) / 256, 256>>>(dst, batch, n, E);
    scan_block<<<1, 1024>>>(n);
    // #4 GEMM layer 1 + CSR scatter fused (y==2 slice)
    gemm_mma<IN_DIM, 3, false><<<dim3(ntiles, 3), 256, SMEM64>>>(n, src, dst, E);
    // #5 attention layer 1 + BN stats + B prep for hidden layer 0
    attn_fused<<<NB + 256, 256>>>(n, NB, bn1g, bn1b, Wq, Wk, Wv, Ws, bq, bk, bv, bs);

    for (int i = 0; i < Ld; i++) {
        gemm_mma<Hd, 2, true><<<dim3(ntiles, 2), 256, SMEM128>>>(n, nullptr, nullptr, 0);
        int last = (i == Ld - 1);
        const float* nWq = last ? nullptr : Wq + (size_t)(i + 1) * Hd * Hd;
        const float* nWk = last ? nullptr : Wk + (size_t)(i + 1) * Hd * Hd;
        const float* nWv = last ? nullptr : Wv + (size_t)(i + 1) * Hd * Hd;
        const float* nWs = last ? nullptr : Ws + (size_t)(i + 1) * Hd * Hd;
        const float* nbq = last ? nullptr : bq + (i + 1) * Hd;
        const float* nbk = last ? nullptr : bk + (i + 1) * Hd;
        const float* nbv = last ? nullptr : bv + (i + 1) * Hd;
        const float* nbs = last ? nullptr : bs + (i + 1) * Hd;
        attn_fused<<<NB + 256, 256>>>(n, NB, bng + i * Hd, bnb + i * Hd,
                                      nWq, nWk, nWv, nWs, nbq, nbk, nbv, nbs);
    }

    bn_pool<<<512, 256>>>(n, batch);
    classify<<<Gg, 32>>>(linW, linb, (float*)d_out);
}

// round 14
// speedup vs baseline: 1.1375x; 1.1375x over previous
#include <cuda_runtime.h>
#include <cuda_bf16.h>
#include <math.h>
#include <stdint.h>

// Problem constants
#define Nn 100000
#define Ee 600000
#define IN_DIM 64
#define Hd 128
#define Ld 3
#define Gg 256
#define Cc 10
#define NTILES ((Nn + 127) / 128)

// ---------------- device scratch ----------------
__device__ float  g_h[(size_t)Nn * Hd];
__device__ float  g_q[(size_t)Nn * Hd];
__device__ float  g_s[(size_t)Nn * Hd];
__device__ __align__(16) __nv_bfloat16 g_kv[(size_t)Nn * 256]; // k|v bf16
__device__ double g_sum[Hd];
__device__ double g_sumsq[Hd];
__device__ float  g_scale[Hd];
__device__ float  g_shift[Hd];
__device__ float  g_pool[Gg * Hd];
__device__ float  g_cnt[Gg];
__device__ int    g_ctr;
// CSR
__device__ int    g_deg[Nn];
__device__ int    g_off[Nn + 1];
__device__ int    g_srcSorted[Ee];
// bf16 hi/lo split staging (layer-1 A image + current-layer B)
__device__ __align__(16) __nv_bfloat16 g_Ahi[(size_t)NTILES * 128 * IN_DIM];
__device__ __align__(16) __nv_bfloat16 g_Alo[(size_t)NTILES * 128 * IN_DIM];
__device__ __align__(16) __nv_bfloat16 g_Bhi[512 * 128];
__device__ __align__(16) __nv_bfloat16 g_Blo[512 * 128];
__device__ float  g_bias[512];

// ---------------- asm helpers ----------------
__device__ __forceinline__ uint32_t smem_u32(const void* p) {
    uint32_t a;
    asm("{ .reg .u64 t; cvta.to.shared.u64 t, %1; cvt.u32.u64 %0, t; }" : "=r"(a) : "l"(p));
    return a;
}

__device__ __forceinline__ void mma16816(float* d,
    uint32_t a0, uint32_t a1, uint32_t a2, uint32_t a3,
    uint32_t b0, uint32_t b1)
{
    asm volatile(
        "mma.sync.aligned.m16n8k16.row.col.f32.bf16.bf16.f32 "
        "{%0,%1,%2,%3}, {%4,%5,%6,%7}, {%8,%9}, {%0,%1,%2,%3};"
        : "+f"(d[0]), "+f"(d[1]), "+f"(d[2]), "+f"(d[3])
        : "r"(a0), "r"(a1), "r"(a2), "r"(a3), "r"(b0), "r"(b1));
}

__device__ __forceinline__ void ldsm4(uint32_t* r, uint32_t addr) {
    asm volatile("ldmatrix.sync.aligned.m8n8.x4.shared.b16 {%0,%1,%2,%3}, [%4];"
        : "=r"(r[0]), "=r"(r[1]), "=r"(r[2]), "=r"(r[3]) : "r"(addr));
}

#define CP_ASYNC16(dst, src) \
    asm volatile("cp.async.cg.shared.global [%0], [%1], 16;" :: "r"(dst), "l"(src))
#define CP_COMMIT()  asm volatile("cp.async.commit_group;" ::: "memory")

__device__ __forceinline__ float4 ld_bf4(const __nv_bfloat16* p) {
    uint2 u = *(const uint2*)p;
    __nv_bfloat162 a = *reinterpret_cast<__nv_bfloat162*>(&u.x);
    __nv_bfloat162 b = *reinterpret_cast<__nv_bfloat162*>(&u.y);
    float2 fa = __bfloat1622float2(a), fb = __bfloat1622float2(b);
    return make_float4(fa.x, fa.y, fb.x, fb.y);
}

// ---------------- fused layer-1 prep (+ deg zero) ----------------
__global__ void prep_layer1(const float* __restrict__ x, int n, int ntiles,
                            const float* __restrict__ Wq, const float* __restrict__ Wk,
                            const float* __restrict__ Wv, const float* __restrict__ Ws,
                            const float* __restrict__ bq, const float* __restrict__ bk,
                            const float* __restrict__ bv, const float* __restrict__ bs)
{
    long aTot = (long)ntiles * 128 * IN_DIM;
    long bTot = 512 * IN_DIM;
    long total = aTot + bTot + 512 + n;
    long stride = (long)gridDim.x * blockDim.x;
    for (long idx = (long)blockIdx.x * blockDim.x + threadIdx.x; idx < total; idx += stride) {
        if (idx < aTot) {
            long row = idx / IN_DIM;
            int  k = (int)(idx % IN_DIM);
            float v = (row < n) ? x[row * IN_DIM + k] : 0.f;
            __nv_bfloat16 hi = __float2bfloat16(v);
            g_Ahi[idx] = hi;
            g_Alo[idx] = __float2bfloat16(v - __bfloat162float(hi));
        } else if (idx < aTot + bTot) {
            int j = (int)(idx - aTot);
            int nglob = j / IN_DIM, k = j % IN_DIM;
            int w = nglob >> 7, nloc = nglob & 127;
            const float* W = (w == 0) ? Wq : (w == 1) ? Wk : (w == 2) ? Wv : Ws;
            float v = W[(size_t)k * Hd + nloc];
            __nv_bfloat16 hi = __float2bfloat16(v);
            g_Bhi[j] = hi;
            g_Blo[j] = __float2bfloat16(v - __bfloat162float(hi));
        } else if (idx < aTot + bTot + 512) {
            int nglob = (int)(idx - aTot - bTot);
            int w = nglob >> 7, nloc = nglob & 127;
            const float* B = (w == 0) ? bq : (w == 1) ? bk : (w == 2) ? bv : bs;
            g_bias[nglob] = B[nloc];
        } else {
            g_deg[idx - aTot - bTot - 512] = 0;
        }
    }
}

// ---------------- setup2 ----------------
__global__ void setup2(const int* __restrict__ dst, const int* __restrict__ batch,
                       int n, int E) {
    int idx = blockIdx.x * blockDim.x + threadIdx.x;
    if (idx < E) atomicAdd(&g_deg[dst[idx]], 1);
    if (idx == 0) { g_off[0] = 0; g_ctr = 0; }
    if (idx < Hd) { g_sum[idx] = 0.0; g_sumsq[idx] = 0.0; }
    if (idx < Gg * Hd) g_pool[idx] = 0.f;
    if (idx < Gg) {
        int g = idx;
        int lo = 0, hi = n;
        while (lo < hi) { int mid = (lo + hi) >> 1; if (batch[mid] < g) lo = mid + 1; else hi = mid; }
        int lb = lo;
        lo = 0; hi = n;
        while (lo < hi) { int mid = (lo + hi) >> 1; if (batch[mid] <= g) lo = mid + 1; else hi = mid; }
        g_cnt[g] = (float)(lo - lb);
    }
}

__global__ void __launch_bounds__(1024) scan_block(int n) {
    __shared__ int sh[1024];
    int t = threadIdx.x;
    int chunk = (n + 1023) >> 10;
    int s0 = min(t * chunk, n), s1 = min(s0 + chunk, n);
    int s = 0;
    for (int i = s0; i < s1; i++) s += g_deg[i];
    sh[t] = s;
    __syncthreads();
    #pragma unroll
    for (int d = 1; d < 1024; d <<= 1) {
        int v = (t >= d) ? sh[t - d] : 0;
        __syncthreads();
        sh[t] += v;
        __syncthreads();
    }
    int run = (t == 0) ? 0 : sh[t - 1];
    for (int i = s0; i < s1; i++) {
        int d = g_deg[i];
        g_deg[i] = run;
        run += d;
        g_off[i + 1] = run;
    }
}

__global__ void csr_scatter(const int* __restrict__ src, const int* __restrict__ dst, int E) {
    int e = blockIdx.x * blockDim.x + threadIdx.x;
    if (e >= E) return;
    int pos = atomicAdd(&g_deg[dst[e]], 1);
    g_srcSorted[pos] = src[e];
}

// ---------------- GEMM (exact R8) ----------------
#define BSTR 40
#define BTSZ (128 * BSTR)

template<int K, int S, bool FUSE>
__global__ void __launch_bounds__(256, 2) gemm_mma(int n) {
    constexpr int ASTR = K + 8;
    constexpr int ATSZ = 128 * ASTR;
    constexpr int NK = K / 32;
    constexpr int P = 2 * NK;
    extern __shared__ __nv_bfloat16 sm[];
    const int B_OFF = 2 * ATSZ;

    const int tid = threadIdx.x;
    const int tile = blockIdx.x;
    const int cb = blockIdx.y * 2;
    const int wid = tid >> 5, lane = tid & 31;
    const int wm = (wid & 3) * 32, wn = (wid >> 2) * 64;
    const int gid = lane >> 2, tig = lane & 3;
    const uint32_t smb = smem_u32(sm);

    auto stageB = [&](int pp) {
        int buf = pp % S;
        int cc = cb + pp / NK;
        int kt = (pp % NK) * 32;
        #pragma unroll
        for (int t = 0; t < 4; t++) {
            int idx = tid + t * 256;
            int img = idx >> 9, rem = idx & 511;
            int r = rem >> 2, c = rem & 3;
            const __nv_bfloat16* sp = (img ? g_Blo : g_Bhi) + (size_t)(cc * 128 + r) * K + kt + c * 8;
            uint32_t d = smb + (uint32_t)(B_OFF + buf * 2 * BTSZ + img * BTSZ + r * BSTR + c * 8) * 2;
            CP_ASYNC16(d, sp);
        }
        CP_COMMIT();
    };

    if (FUSE) {
        #pragma unroll
        for (int s = 0; s < S - 1; s++) stageB(s);
        const int cg = (tid & 31) * 4;
        const float4 sc4 = *(const float4*)(g_scale + cg);
        const float4 sh4 = *(const float4*)(g_shift + cg);
        #pragma unroll
        for (int t = 0; t < 16; t++) {
            int idx = tid + t * 256;
            int r = idx >> 5;
            long grow = (long)tile * 128 + r;
            float4 v = make_float4(0.f, 0.f, 0.f, 0.f);
            if (grow < n) v = *(const float4*)(g_h + grow * 128 + cg);
            v.x = fmaxf(v.x * sc4.x + sh4.x, 0.f);
            v.y = fmaxf(v.y * sc4.y + sh4.y, 0.f);
            v.z = fmaxf(v.z * sc4.z + sh4.z, 0.f);
            v.w = fmaxf(v.w * sc4.w + sh4.w, 0.f);
            __nv_bfloat162 h0 = __floats2bfloat162_rn(v.x, v.y);
            __nv_bfloat162 h1 = __floats2bfloat162_rn(v.z, v.w);
            float2 f0 = __bfloat1622float2(h0), f1 = __bfloat1622float2(h1);
            __nv_bfloat162 l0 = __floats2bfloat162_rn(v.x - f0.x, v.y - f0.y);
            __nv_bfloat162 l1 = __floats2bfloat162_rn(v.z - f1.x, v.w - f1.y);
            uint2 uh, ul;
            uh.x = *(uint32_t*)&h0; uh.y = *(uint32_t*)&h1;
            ul.x = *(uint32_t*)&l0; ul.y = *(uint32_t*)&l1;
            *(uint2*)&sm[r * ASTR + cg] = uh;
            *(uint2*)&sm[ATSZ + r * ASTR + cg] = ul;
        }
    } else {
        const __nv_bfloat16* aH = g_Ahi + (size_t)tile * 128 * K;
        const __nv_bfloat16* aL = g_Alo + (size_t)tile * 128 * K;
        constexpr int ACH = 2 * 128 * (K / 8);
        #pragma unroll
        for (int t = 0; t < ACH / 256; t++) {
            int i = tid + t * 256;
            int img = i / (128 * (K / 8));
            int rem = i % (128 * (K / 8));
            int r = rem / (K / 8), c = rem % (K / 8);
            const __nv_bfloat16* sp = (img ? aL : aH) + (size_t)r * K + c * 8;
            uint32_t d = smb + (uint32_t)(img * ATSZ + r * ASTR + c * 8) * 2;
            CP_ASYNC16(d, sp);
        }
        #pragma unroll
        for (int s = 0; s < S - 1; s++) stageB(s);
    }

    float acc[2][8][4] = {};

    #pragma unroll 1
    for (int p = 0; p < P; p++) {
        if (p + S - 1 < P) {
            stageB(p + S - 1);
            asm volatile("cp.async.wait_group %0;" :: "n"(S - 1) : "memory");
        } else {
            asm volatile("cp.async.wait_group 0;" ::: "memory");
        }
        __syncthreads();

        const int ktA = (p % NK) * 32;
        const uint32_t bbase = smb + (uint32_t)(B_OFF + (p % S) * 2 * BTSZ) * 2;

        #pragma unroll
        for (int ks = 0; ks < 2; ks++) {
            const int kb = ks * 16;
            uint32_t ah[2][4], al[2][4];
            #pragma unroll
            for (int mt = 0; mt < 2; mt++) {
                int row = wm + mt * 16 + (lane & 15);
                int col = ktA + kb + ((lane & 16) ? 8 : 0);
                uint32_t ad = smb + (uint32_t)(row * ASTR + col) * 2;
                ldsm4(ah[mt], ad);
                ldsm4(al[mt], ad + ATSZ * 2);
            }
            #pragma unroll
            for (int ntp = 0; ntp < 4; ntp++) {
                int row = wn + ntp * 16 + (lane & 7) + ((lane & 16) ? 8 : 0);
                int col = kb + ((lane & 8) ? 8 : 0);
                uint32_t bd = bbase + (uint32_t)(2 * 0 + row * BSTR + col) * 2;
                uint32_t bh[4], bl[4];
                ldsm4(bh, bd);
                ldsm4(bl, bd + BTSZ * 2);
                #pragma unroll
                for (int sub = 0; sub < 2; sub++) {
                    int nt = ntp * 2 + sub;
                    #pragma unroll
                    for (int mt = 0; mt < 2; mt++) {
                        mma16816(acc[mt][nt], ah[mt][0], ah[mt][1], ah[mt][2], ah[mt][3], bh[sub*2], bh[sub*2+1]);
                        mma16816(acc[mt][nt], ah[mt][0], ah[mt][1], ah[mt][2], ah[mt][3], bl[sub*2], bl[sub*2+1]);
                        mma16816(acc[mt][nt], al[mt][0], al[mt][1], al[mt][2], al[mt][3], bh[sub*2], bh[sub*2+1]);
                    }
                }
            }
        }
        __syncthreads();

        if ((p % NK) == NK - 1) {
            const int cc = cb + p / NK;
            #pragma unroll
            for (int mt = 0; mt < 2; mt++) {
                long r0 = (long)tile * 128 + wm + mt * 16 + gid;
                #pragma unroll
                for (int nt = 0; nt < 8; nt++) {
                    int col = wn + nt * 8 + tig * 2;
                    float b0 = g_bias[cc * 128 + col], b1 = g_bias[cc * 128 + col + 1];
                    float v0 = acc[mt][nt][0] + b0, v1 = acc[mt][nt][1] + b1;
                    float v2 = acc[mt][nt][2] + b0, v3 = acc[mt][nt][3] + b1;
                    if (cc == 0) {
                        if (r0 < n)     *(float2*)(g_q + r0 * 128 + col)       = make_float2(v0, v1);
                        if (r0 + 8 < n) *(float2*)(g_q + (r0 + 8) * 128 + col) = make_float2(v2, v3);
                    } else if (cc == 3) {
                        if (r0 < n)     *(float2*)(g_s + r0 * 128 + col)       = make_float2(v0, v1);
                        if (r0 + 8 < n) *(float2*)(g_s + (r0 + 8) * 128 + col) = make_float2(v2, v3);
                    } else {
                        int off = (cc == 2) ? 128 : 0;
                        __nv_bfloat162 p0 = __floats2bfloat162_rn(v0, v1);
                        __nv_bfloat162 p1 = __floats2bfloat162_rn(v2, v3);
                        if (r0 < n)     *(__nv_bfloat162*)(g_kv + r0 * 256 + off + col)       = p0;
                        if (r0 + 8 < n) *(__nv_bfloat162*)(g_kv + (r0 + 8) * 256 + off + col) = p1;
                    }
                    acc[mt][nt][0] = 0.f; acc[mt][nt][1] = 0.f;
                    acc[mt][nt][2] = 0.f; acc[mt][nt][3] = 0.f;
                }
            }
        }
    }
}

// ---------------- attention v6: single-pass, no max-subtraction ----------------
__global__ void __launch_bounds__(256) attn_fused(int n, int NB,
        const float* __restrict__ gamma, const float* __restrict__ beta,
        const float* __restrict__ Wq, const float* __restrict__ Wk,
        const float* __restrict__ Wv, const float* __restrict__ Ws,
        const float* __restrict__ bq, const float* __restrict__ bk,
        const float* __restrict__ bv, const float* __restrict__ bs) {
    if ((int)blockIdx.x >= NB) {
        if (Wq) {
            int idx = ((int)blockIdx.x - NB) * 256 + threadIdx.x;
            int nglob = idx / Hd, k = idx % Hd;
            int w = nglob >> 7, nloc = nglob & 127;
            const float* W = (w == 0) ? Wq : (w == 1) ? Wk : (w == 2) ? Wv : Ws;
            float v = W[(size_t)k * Hd + nloc];
            __nv_bfloat16 hi = __float2bfloat16(v);
            g_Bhi[idx] = hi;
            g_Blo[idx] = __float2bfloat16(v - __bfloat162float(hi));
            if (k == 0) {
                const float* B = (w == 0) ? bq : (w == 1) ? bk : (w == 2) ? bv : bs;
                g_bias[nglob] = B[nloc];
            }
        }
        return;
    }

    __shared__ float ssum[Hd], ssq[Hd];
    __shared__ int sh_last;
    for (int i = threadIdx.x; i < Hd; i += 256) { ssum[i] = 0.f; ssq[i] = 0.f; }
    __syncthreads();

    const int lane = threadIdx.x & 31;
    const int c0 = lane * 4;
    const int wstride = NB * 8;
    const float SCALE = 0.08838834764831845f;
    float ls0 = 0.f, ls1 = 0.f, ls2 = 0.f, ls3 = 0.f;
    float lq0 = 0.f, lq1 = 0.f, lq2 = 0.f, lq3 = 0.f;

    for (int node = blockIdx.x * 8 + (threadIdx.x >> 5); node < n; node += wstride) {
        const int off0 = g_off[node];
        const int deg  = g_off[node + 1] - off0;
        const float4 q = *(const float4*)(g_q + (size_t)node * 128 + c0);

        float sum = 0.f;
        float ax = 0.f, ay = 0.f, az = 0.f, aw = 0.f;

        for (int base = 0; base < deg; base += 32) {
            const int c = min(32, deg - base);
            int myidx = (lane < c) ? g_srcSorted[off0 + base + lane] : 0;

            #pragma unroll 4
            for (int j = 0; j < c; j++) {
                int s = __shfl_sync(0xffffffffu, myidx, j);
                const __nv_bfloat16* row = g_kv + (size_t)s * 256;
                float4 kk = ld_bf4(row + c0);
                float4 vv = ld_bf4(row + 128 + c0);
                float p = q.x * kk.x + q.y * kk.y + q.z * kk.z + q.w * kk.w;
                #pragma unroll
                for (int o = 16; o; o >>= 1) p += __shfl_xor_sync(0xffffffffu, p, o);
                float w = __expf(p * SCALE);   // |p*SCALE| small: max-shift unnecessary
                ax += w * vv.x;
                ay += w * vv.y;
                az += w * vv.z;
                aw += w * vv.w;
                sum += w;
            }
        }

        float inv = (deg > 0) ? 1.f / sum : 0.f;
        float4 sk = *(const float4*)(g_s + (size_t)node * 128 + c0);
        float h0 = ax * inv + sk.x;
        float h1 = ay * inv + sk.y;
        float h2 = az * inv + sk.z;
        float h3 = aw * inv + sk.w;
        *(float4*)(g_h + (size_t)node * Hd + c0) = make_float4(h0, h1, h2, h3);
        ls0 += h0; ls1 += h1; ls2 += h2; ls3 += h3;
        lq0 += h0 * h0; lq1 += h1 * h1; lq2 += h2 * h2; lq3 += h3 * h3;
    }

    atomicAdd(&ssum[c0 + 0], ls0); atomicAdd(&ssq[c0 + 0], lq0);
    atomicAdd(&ssum[c0 + 1], ls1); atomicAdd(&ssq[c0 + 1], lq1);
    atomicAdd(&ssum[c0 + 2], ls2); atomicAdd(&ssq[c0 + 2], lq2);
    atomicAdd(&ssum[c0 + 3], ls3); atomicAdd(&ssq[c0 + 3], lq3);
    __syncthreads();
    if (threadIdx.x < Hd) {
        atomicAdd(&g_sum[threadIdx.x], (double)ssum[threadIdx.x]);
        atomicAdd(&g_sumsq[threadIdx.x], (double)ssq[threadIdx.x]);
    }

    __threadfence();
    if (threadIdx.x == 0) {
        int t = atomicAdd(&g_ctr, 1);
        sh_last = (t == NB - 1);
    }
    __syncthreads();
    if (sh_last) {
        int ch = threadIdx.x;
        if (ch < Hd) {
            double mean = g_sum[ch] / n;
            double var  = g_sumsq[ch] / n - mean * mean;
            if (var < 0.0) var = 0.0;
            float invs = (float)rsqrt(var + 1e-5);
            float scv = invs * gamma[ch];
            g_scale[ch] = scv;
            g_shift[ch] = beta[ch] - (float)mean * scv;
            g_sum[ch] = 0.0;
            g_sumsq[ch] = 0.0;
        }
        if (threadIdx.x == 0) g_ctr = 0;
    }
}

// ---------------- last-layer BN apply + pool ----------------
__global__ void bn_pool(int n, const int* __restrict__ batch) {
    long stride = (long)gridDim.x * blockDim.x;
    long total = (long)n * Hd;
    for (long i = (long)blockIdx.x * blockDim.x + threadIdx.x; i < total; i += stride) {
        int c = (int)(i & 127);
        float v = fmaxf(g_h[i] * g_scale[c] + g_shift[c], 0.f);
        int node = (int)(i >> 7);
        atomicAdd(&g_pool[batch[node] * Hd + c], v);
    }
}

__global__ void classify(const float* __restrict__ W, const float* __restrict__ b,
                         float* __restrict__ out) {
    int g = blockIdx.x;
    int c = threadIdx.x;
    if (c >= Cc) return;
    float inv = 1.f / fmaxf(g_cnt[g], 1.f);
    float acc = 0.f;
    #pragma unroll 8
    for (int h = 0; h < Hd; h++) acc += g_pool[g * Hd + h] * W[h * Cc + c];
    out[g * Cc + c] = acc * inv + b[c];
}

// ---------------- host orchestration ----------------
extern "C" void kernel_launch(void* const* d_in, const int* in_sizes, int n_in,
                              void* d_out, int out_size)
{
    const float* x     = (const float*)d_in[0];
    const int*   ei    = (const int*)d_in[1];
    const int*   batch = (const int*)d_in[2];
    const float* Wq1 = (const float*)d_in[3];
    const float* bq1 = (const float*)d_in[4];
    const float* Wk1 = (const float*)d_in[5];
    const float* bk1 = (const float*)d_in[6];
    const float* Wv1 = (const float*)d_in[7];
    const float* bv1 = (const float*)d_in[8];
    const float* Ws1 = (const float*)d_in[9];
    const float* bs1 = (const float*)d_in[10];
    const float* bn1g = (const float*)d_in[11];
    const float* bn1b = (const float*)d_in[12];
    const float* Wq = (const float*)d_in[13];
    const float* bq = (const float*)d_in[14];
    const float* Wk = (const float*)d_in[15];
    const float* bk = (const float*)d_in[16];
    const float* Wv = (const float*)d_in[17];
    const float* bv = (const float*)d_in[18];
    const float* Ws = (const float*)d_in[19];
    const float* bs = (const float*)d_in[20];
    const float* bng = (const float*)d_in[21];
    const float* bnb = (const float*)d_in[22];
    const float* linW = (const float*)d_in[23];
    const float* linb = (const float*)d_in[24];

    int n = in_sizes[0] / IN_DIM;
    int E = in_sizes[1] / 2;
    int ntiles = (n + 127) / 128;
    const int* src = ei;
    const int* dst = ei + E;
    const int NB = 2048;

    const int SMEM64  = (2 * 128 * (IN_DIM + 8)) * 2 + 3 * 2 * BTSZ * 2;  // 98304
    const int SMEM128 = (2 * 128 * (Hd + 8)) * 2 + 2 * 2 * BTSZ * 2;      // 110592
    cudaFuncSetAttribute((const void*)gemm_mma<IN_DIM, 3, false>, cudaFuncAttributeMaxDynamicSharedMemorySize, SMEM64);
    cudaFuncSetAttribute((const void*)gemm_mma<Hd, 2, true>,      cudaFuncAttributeMaxDynamicSharedMemorySize, SMEM128);

    // #1 prep, #2 setup, #3 scan  (exact R8 sequence)
    prep_layer1<<<1024, 256>>>(x, n, ntiles, Wq1, Wk1, Wv1, Ws1, bq1, bk1, bv1, bs1);
    setup2<<<(E + 255) / 256, 256>>>(dst, batch, n, E);
    scan_block<<<1, 1024>>>(n);
    // #4 GEMM layer 1
    gemm_mma<IN_DIM, 3, false><<<dim3(ntiles, 2), 256, SMEM64>>>(n);
    // #5 scatter
    csr_scatter<<<(E + 255) / 256, 256>>>(src, dst, E);
    // #6 attention layer 1 + BN stats + B prep for hidden layer 0
    attn_fused<<<NB + 256, 256>>>(n, NB, bn1g, bn1b, Wq, Wk, Wv, Ws, bq, bk, bv, bs);

    for (int i = 0; i < Ld; i++) {
        gemm_mma<Hd, 2, true><<<dim3(ntiles, 2), 256, SMEM128>>>(n);
        int last = (i == Ld - 1);
        const float* nWq = last ? nullptr : Wq + (size_t)(i + 1) * Hd * Hd;
        const float* nWk = last ? nullptr : Wk + (size_t)(i + 1) * Hd * Hd;
        const float* nWv = last ? nullptr : Wv + (size_t)(i + 1) * Hd * Hd;
        const float* nWs = last ? nullptr : Ws + (size_t)(i + 1) * Hd * Hd;
        const float* nbq = last ? nullptr : bq + (i + 1) * Hd;
        const float* nbk = last ? nullptr : bk + (i + 1) * Hd;
        const float* nbv = last ? nullptr : bv + (i + 1) * Hd;
        const float* nbs = last ? nullptr : bs + (i + 1) * Hd;
        attn_fused<<<NB + 256, 256>>>(n, NB, bng + i * Hd, bnb + i * Hd,
                                      nWq, nWk, nWv, nWs, nbq, nbk, nbv, nbs);
    }

    bn_pool<<<512, 256>>>(n, batch);
    classify<<<Gg, 32>>>(linW, linb, (float*)d_out);
}

// round 15
// speedup vs baseline: 1.2524x; 1.1010x over previous
#include <cuda_runtime.h>
#include <cuda_bf16.h>
#include <cuda_fp16.h>
#include <math.h>
#include <stdint.h>

// Problem constants
#define Nn 100000
#define Ee 600000
#define IN_DIM 64
#define Hd 128
#define Ld 3
#define Gg 256
#define Cc 10
#define NTILES ((Nn + 127) / 128)

// ---------------- device scratch ----------------
__device__ float  g_h[(size_t)Nn * Hd];
__device__ float  g_q[(size_t)Nn * Hd];
__device__ float  g_s[(size_t)Nn * Hd];
__device__ __align__(16) __nv_bfloat16 g_kv[(size_t)Nn * 256]; // k|v bf16
__device__ double g_sum[Hd];
__device__ double g_sumsq[Hd];
__device__ float  g_scale[Hd];
__device__ float  g_shift[Hd];
__device__ float  g_pool[Gg * Hd];
__device__ float  g_cnt[Gg];
__device__ int    g_ctr;
// CSR
__device__ int    g_deg[Nn];
__device__ int    g_off[Nn + 1];
__device__ int    g_srcSorted[Ee];
// fp16 staging: A single image (layer-1), B hi/lo split (current layer)
__device__ __align__(16) __half g_Ah[(size_t)NTILES * 128 * IN_DIM];
__device__ __align__(16) __half g_Bhi[512 * 128];
__device__ __align__(16) __half g_Blo[512 * 128];
__device__ float  g_bias[512];

// ---------------- asm helpers ----------------
__device__ __forceinline__ uint32_t smem_u32(const void* p) {
    uint32_t a;
    asm("{ .reg .u64 t; cvta.to.shared.u64 t, %1; cvt.u32.u64 %0, t; }" : "=r"(a) : "l"(p));
    return a;
}

__device__ __forceinline__ void mma16816h(float* d,
    uint32_t a0, uint32_t a1, uint32_t a2, uint32_t a3,
    uint32_t b0, uint32_t b1)
{
    asm volatile(
        "mma.sync.aligned.m16n8k16.row.col.f32.f16.f16.f32 "
        "{%0,%1,%2,%3}, {%4,%5,%6,%7}, {%8,%9}, {%0,%1,%2,%3};"
        : "+f"(d[0]), "+f"(d[1]), "+f"(d[2]), "+f"(d[3])
        : "r"(a0), "r"(a1), "r"(a2), "r"(a3), "r"(b0), "r"(b1));
}

__device__ __forceinline__ void ldsm4(uint32_t* r, uint32_t addr) {
    asm volatile("ldmatrix.sync.aligned.m8n8.x4.shared.b16 {%0,%1,%2,%3}, [%4];"
        : "=r"(r[0]), "=r"(r[1]), "=r"(r[2]), "=r"(r[3]) : "r"(addr));
}

#define CP_ASYNC16(dst, src) \
    asm volatile("cp.async.cg.shared.global [%0], [%1], 16;" :: "r"(dst), "l"(src))
#define CP_COMMIT()  asm volatile("cp.async.commit_group;" ::: "memory")

__device__ __forceinline__ float4 ld_bf4(const __nv_bfloat16* p) {
    uint2 u = *(const uint2*)p;
    __nv_bfloat162 a = *reinterpret_cast<__nv_bfloat162*>(&u.x);
    __nv_bfloat162 b = *reinterpret_cast<__nv_bfloat162*>(&u.y);
    float2 fa = __bfloat1622float2(a), fb = __bfloat1622float2(b);
    return make_float4(fa.x, fa.y, fb.x, fb.y);
}

// ---------------- fused layer-1 prep (+ deg zero) ----------------
__global__ void prep_layer1(const float* __restrict__ x, int n, int ntiles,
                            const float* __restrict__ Wq, const float* __restrict__ Wk,
                            const float* __restrict__ Wv, const float* __restrict__ Ws,
                            const float* __restrict__ bq, const float* __restrict__ bk,
                            const float* __restrict__ bv, const float* __restrict__ bs)
{
    long aTot = (long)ntiles * 128 * IN_DIM;
    long bTot = 512 * IN_DIM;
    long total = aTot + bTot + 512 + n;
    long stride = (long)gridDim.x * blockDim.x;
    for (long idx = (long)blockIdx.x * blockDim.x + threadIdx.x; idx < total; idx += stride) {
        if (idx < aTot) {
            long row = idx / IN_DIM;
            int  k = (int)(idx % IN_DIM);
            float v = (row < n) ? x[row * IN_DIM + k] : 0.f;
            g_Ah[idx] = __float2half(v);
        } else if (idx < aTot + bTot) {
            int j = (int)(idx - aTot);
            int nglob = j / IN_DIM, k = j % IN_DIM;
            int w = nglob >> 7, nloc = nglob & 127;
            const float* W = (w == 0) ? Wq : (w == 1) ? Wk : (w == 2) ? Wv : Ws;
            float v = W[(size_t)k * Hd + nloc];
            __half hi = __float2half(v);
            g_Bhi[j] = hi;
            g_Blo[j] = __float2half(v - __half2float(hi));
        } else if (idx < aTot + bTot + 512) {
            int nglob = (int)(idx - aTot - bTot);
            int w = nglob >> 7, nloc = nglob & 127;
            const float* B = (w == 0) ? bq : (w == 1) ? bk : (w == 2) ? bv : bs;
            g_bias[nglob] = B[nloc];
        } else {
            g_deg[idx - aTot - bTot - 512] = 0;
        }
    }
}

// ---------------- setup2 ----------------
__global__ void setup2(const int* __restrict__ dst, const int* __restrict__ batch,
                       int n, int E) {
    int idx = blockIdx.x * blockDim.x + threadIdx.x;
    if (idx < E) atomicAdd(&g_deg[dst[idx]], 1);
    if (idx == 0) { g_off[0] = 0; g_ctr = 0; }
    if (idx < Hd) { g_sum[idx] = 0.0; g_sumsq[idx] = 0.0; }
    if (idx < Gg * Hd) g_pool[idx] = 0.f;
    if (idx < Gg) {
        int g = idx;
        int lo = 0, hi = n;
        while (lo < hi) { int mid = (lo + hi) >> 1; if (batch[mid] < g) lo = mid + 1; else hi = mid; }
        int lb = lo;
        lo = 0; hi = n;
        while (lo < hi) { int mid = (lo + hi) >> 1; if (batch[mid] <= g) lo = mid + 1; else hi = mid; }
        g_cnt[g] = (float)(lo - lb);
    }
}

__global__ void __launch_bounds__(1024) scan_block(int n) {
    __shared__ int sh[1024];
    int t = threadIdx.x;
    int chunk = (n + 1023) >> 10;
    int s0 = min(t * chunk, n), s1 = min(s0 + chunk, n);
    int s = 0;
    for (int i = s0; i < s1; i++) s += g_deg[i];
    sh[t] = s;
    __syncthreads();
    #pragma unroll
    for (int d = 1; d < 1024; d <<= 1) {
        int v = (t >= d) ? sh[t - d] : 0;
        __syncthreads();
        sh[t] += v;
        __syncthreads();
    }
    int run = (t == 0) ? 0 : sh[t - 1];
    for (int i = s0; i < s1; i++) {
        int d = g_deg[i];
        g_deg[i] = run;
        run += d;
        g_off[i + 1] = run;
    }
}

__global__ void csr_scatter(const int* __restrict__ src, const int* __restrict__ dst, int E) {
    int e = blockIdx.x * blockDim.x + threadIdx.x;
    if (e >= E) return;
    int pos = atomicAdd(&g_deg[dst[e]], 1);
    g_srcSorted[pos] = src[e];
}

// ---------------- GEMM: fp16, A single image, B hi/lo (2 MMAs) ----------------
#define BSTR 40
#define BTSZ (128 * BSTR)

template<int K, int S, bool FUSE>
__global__ void __launch_bounds__(256, 2) gemm_mma(int n) {
    constexpr int ASTR = K + 8;
    constexpr int ATSZ = 128 * ASTR;        // single A image (fp16)
    constexpr int NK = K / 32;
    constexpr int P = 2 * NK;
    extern __shared__ __half sm[];
    const int B_OFF = ATSZ;

    const int tid = threadIdx.x;
    const int tile = blockIdx.x;
    const int cb = blockIdx.y * 2;
    const int wid = tid >> 5, lane = tid & 31;
    const int wm = (wid & 3) * 32, wn = (wid >> 2) * 64;
    const int gid = lane >> 2, tig = lane & 3;
    const uint32_t smb = smem_u32(sm);

    auto stageB = [&](int pp) {
        int buf = pp % S;
        int cc = cb + pp / NK;
        int kt = (pp % NK) * 32;
        #pragma unroll
        for (int t = 0; t < 4; t++) {
            int idx = tid + t * 256;
            int img = idx >> 9, rem = idx & 511;
            int r = rem >> 2, c = rem & 3;
            const __half* sp = (img ? g_Blo : g_Bhi) + (size_t)(cc * 128 + r) * K + kt + c * 8;
            uint32_t d = smb + (uint32_t)(B_OFF + buf * 2 * BTSZ + img * BTSZ + r * BSTR + c * 8) * 2;
            CP_ASYNC16(d, sp);
        }
        CP_COMMIT();
    };

    if (FUSE) {
        #pragma unroll
        for (int s = 0; s < S - 1; s++) stageB(s);
        const int cg = (tid & 31) * 4;
        const float4 sc4 = *(const float4*)(g_scale + cg);
        const float4 sh4 = *(const float4*)(g_shift + cg);
        #pragma unroll
        for (int t = 0; t < 16; t++) {
            int idx = tid + t * 256;
            int r = idx >> 5;
            long grow = (long)tile * 128 + r;
            float4 v = make_float4(0.f, 0.f, 0.f, 0.f);
            if (grow < n) v = *(const float4*)(g_h + grow * 128 + cg);
            v.x = fmaxf(v.x * sc4.x + sh4.x, 0.f);
            v.y = fmaxf(v.y * sc4.y + sh4.y, 0.f);
            v.z = fmaxf(v.z * sc4.z + sh4.z, 0.f);
            v.w = fmaxf(v.w * sc4.w + sh4.w, 0.f);
            __half2 h0 = __floats2half2_rn(v.x, v.y);
            __half2 h1 = __floats2half2_rn(v.z, v.w);
            uint2 uh;
            uh.x = *(uint32_t*)&h0; uh.y = *(uint32_t*)&h1;
            *(uint2*)&sm[r * ASTR + cg] = uh;
        }
    } else {
        const __half* aP = g_Ah + (size_t)tile * 128 * K;
        constexpr int ACH = 128 * (K / 8);
        #pragma unroll
        for (int t = 0; t < ACH / 256; t++) {
            int i = tid + t * 256;
            int r = i / (K / 8), c = i % (K / 8);
            const __half* sp = aP + (size_t)r * K + c * 8;
            uint32_t d = smb + (uint32_t)(r * ASTR + c * 8) * 2;
            CP_ASYNC16(d, sp);
        }
        #pragma unroll
        for (int s = 0; s < S - 1; s++) stageB(s);
    }

    float acc[2][8][4] = {};

    #pragma unroll 1
    for (int p = 0; p < P; p++) {
        if (p + S - 1 < P) {
            stageB(p + S - 1);
            asm volatile("cp.async.wait_group %0;" :: "n"(S - 1) : "memory");
        } else {
            asm volatile("cp.async.wait_group 0;" ::: "memory");
        }
        __syncthreads();

        const int ktA = (p % NK) * 32;
        const uint32_t bbase = smb + (uint32_t)(B_OFF + (p % S) * 2 * BTSZ) * 2;

        #pragma unroll
        for (int ks = 0; ks < 2; ks++) {
            const int kb = ks * 16;
            uint32_t ah[2][4];
            #pragma unroll
            for (int mt = 0; mt < 2; mt++) {
                int row = wm + mt * 16 + (lane & 15);
                int col = ktA + kb + ((lane & 16) ? 8 : 0);
                uint32_t ad = smb + (uint32_t)(row * ASTR + col) * 2;
                ldsm4(ah[mt], ad);
            }
            #pragma unroll
            for (int ntp = 0; ntp < 4; ntp++) {
                int row = wn + ntp * 16 + (lane & 7) + ((lane & 16) ? 8 : 0);
                int col = kb + ((lane & 8) ? 8 : 0);
                uint32_t bd = bbase + (uint32_t)(row * BSTR + col) * 2;
                uint32_t bh[4], bl[4];
                ldsm4(bh, bd);
                ldsm4(bl, bd + BTSZ * 2);
                #pragma unroll
                for (int sub = 0; sub < 2; sub++) {
                    int nt = ntp * 2 + sub;
                    #pragma unroll
                    for (int mt = 0; mt < 2; mt++) {
                        mma16816h(acc[mt][nt], ah[mt][0], ah[mt][1], ah[mt][2], ah[mt][3], bh[sub*2], bh[sub*2+1]);
                        mma16816h(acc[mt][nt], ah[mt][0], ah[mt][1], ah[mt][2], ah[mt][3], bl[sub*2], bl[sub*2+1]);
                    }
                }
            }
        }
        __syncthreads();

        if ((p % NK) == NK - 1) {
            const int cc = cb + p / NK;
            #pragma unroll
            for (int mt = 0; mt < 2; mt++) {
                long r0 = (long)tile * 128 + wm + mt * 16 + gid;
                #pragma unroll
                for (int nt = 0; nt < 8; nt++) {
                    int col = wn + nt * 8 + tig * 2;
                    float b0 = g_bias[cc * 128 + col], b1 = g_bias[cc * 128 + col + 1];
                    float v0 = acc[mt][nt][0] + b0, v1 = acc[mt][nt][1] + b1;
                    float v2 = acc[mt][nt][2] + b0, v3 = acc[mt][nt][3] + b1;
                    if (cc == 0) {
                        if (r0 < n)     *(float2*)(g_q + r0 * 128 + col)       = make_float2(v0, v1);
                        if (r0 + 8 < n) *(float2*)(g_q + (r0 + 8) * 128 + col) = make_float2(v2, v3);
                    } else if (cc == 3) {
                        if (r0 < n)     *(float2*)(g_s + r0 * 128 + col)       = make_float2(v0, v1);
                        if (r0 + 8 < n) *(float2*)(g_s + (r0 + 8) * 128 + col) = make_float2(v2, v3);
                    } else {
                        int off = (cc == 2) ? 128 : 0;
                        __nv_bfloat162 p0 = __floats2bfloat162_rn(v0, v1);
                        __nv_bfloat162 p1 = __floats2bfloat162_rn(v2, v3);
                        if (r0 < n)     *(__nv_bfloat162*)(g_kv + r0 * 256 + off + col)       = p0;
                        if (r0 + 8 < n) *(__nv_bfloat162*)(g_kv + (r0 + 8) * 256 + off + col) = p1;
                    }
                    acc[mt][nt][0] = 0.f; acc[mt][nt][1] = 0.f;
                    acc[mt][nt][2] = 0.f; acc[mt][nt][3] = 0.f;
                }
            }
        }
    }
}

// ---------------- attention (R14 winner): single-pass, no max-subtraction ----------------
__global__ void __launch_bounds__(256) attn_fused(int n, int NB,
        const float* __restrict__ gamma, const float* __restrict__ beta,
        const float* __restrict__ Wq, const float* __restrict__ Wk,
        const float* __restrict__ Wv, const float* __restrict__ Ws,
        const float* __restrict__ bq, const float* __restrict__ bk,
        const float* __restrict__ bv, const float* __restrict__ bs) {
    if ((int)blockIdx.x >= NB) {
        if (Wq) {
            int idx = ((int)blockIdx.x - NB) * 256 + threadIdx.x;
            int nglob = idx / Hd, k = idx % Hd;
            int w = nglob >> 7, nloc = nglob & 127;
            const float* W = (w == 0) ? Wq : (w == 1) ? Wk : (w == 2) ? Wv : Ws;
            float v = W[(size_t)k * Hd + nloc];
            __half hi = __float2half(v);
            g_Bhi[idx] = hi;
            g_Blo[idx] = __float2half(v - __half2float(hi));
            if (k == 0) {
                const float* B = (w == 0) ? bq : (w == 1) ? bk : (w == 2) ? bv : bs;
                g_bias[nglob] = B[nloc];
            }
        }
        return;
    }

    __shared__ float ssum[Hd], ssq[Hd];
    __shared__ int sh_last;
    for (int i = threadIdx.x; i < Hd; i += 256) { ssum[i] = 0.f; ssq[i] = 0.f; }
    __syncthreads();

    const int lane = threadIdx.x & 31;
    const int c0 = lane * 4;
    const int wstride = NB * 8;
    const float SCALE = 0.08838834764831845f;
    float ls0 = 0.f, ls1 = 0.f, ls2 = 0.f, ls3 = 0.f;
    float lq0 = 0.f, lq1 = 0.f, lq2 = 0.f, lq3 = 0.f;

    for (int node = blockIdx.x * 8 + (threadIdx.x >> 5); node < n; node += wstride) {
        const int off0 = g_off[node];
        const int deg  = g_off[node + 1] - off0;
        const float4 q = *(const float4*)(g_q + (size_t)node * 128 + c0);

        float sum = 0.f;
        float ax = 0.f, ay = 0.f, az = 0.f, aw = 0.f;

        for (int base = 0; base < deg; base += 32) {
            const int c = min(32, deg - base);
            int myidx = (lane < c) ? g_srcSorted[off0 + base + lane] : 0;

            #pragma unroll 4
            for (int j = 0; j < c; j++) {
                int s = __shfl_sync(0xffffffffu, myidx, j);
                const __nv_bfloat16* row = g_kv + (size_t)s * 256;
                float4 kk = ld_bf4(row + c0);
                float4 vv = ld_bf4(row + 128 + c0);
                float p = q.x * kk.x + q.y * kk.y + q.z * kk.z + q.w * kk.w;
                #pragma unroll
                for (int o = 16; o; o >>= 1) p += __shfl_xor_sync(0xffffffffu, p, o);
                float w = __expf(p * SCALE);
                ax += w * vv.x;
                ay += w * vv.y;
                az += w * vv.z;
                aw += w * vv.w;
                sum += w;
            }
        }

        float inv = (deg > 0) ? 1.f / sum : 0.f;
        float4 sk = *(const float4*)(g_s + (size_t)node * 128 + c0);
        float h0 = ax * inv + sk.x;
        float h1 = ay * inv + sk.y;
        float h2 = az * inv + sk.z;
        float h3 = aw * inv + sk.w;
        *(float4*)(g_h + (size_t)node * Hd + c0) = make_float4(h0, h1, h2, h3);
        ls0 += h0; ls1 += h1; ls2 += h2; ls3 += h3;
        lq0 += h0 * h0; lq1 += h1 * h1; lq2 += h2 * h2; lq3 += h3 * h3;
    }

    atomicAdd(&ssum[c0 + 0], ls0); atomicAdd(&ssq[c0 + 0], lq0);
    atomicAdd(&ssum[c0 + 1], ls1); atomicAdd(&ssq[c0 + 1], lq1);
    atomicAdd(&ssum[c0 + 2], ls2); atomicAdd(&ssq[c0 + 2], lq2);
    atomicAdd(&ssum[c0 + 3], ls3); atomicAdd(&ssq[c0 + 3], lq3);
    __syncthreads();
    if (threadIdx.x < Hd) {
        atomicAdd(&g_sum[threadIdx.x], (double)ssum[threadIdx.x]);
        atomicAdd(&g_sumsq[threadIdx.x], (double)ssq[threadIdx.x]);
    }

    __threadfence();
    if (threadIdx.x == 0) {
        int t = atomicAdd(&g_ctr, 1);
        sh_last = (t == NB - 1);
    }
    __syncthreads();
    if (sh_last) {
        int ch = threadIdx.x;
        if (ch < Hd) {
            double mean = g_sum[ch] / n;
            double var  = g_sumsq[ch] / n - mean * mean;
            if (var < 0.0) var = 0.0;
            float invs = (float)rsqrt(var + 1e-5);
            float scv = invs * gamma[ch];
            g_scale[ch] = scv;
            g_shift[ch] = beta[ch] - (float)mean * scv;
            g_sum[ch] = 0.0;
            g_sumsq[ch] = 0.0;
        }
        if (threadIdx.x == 0) g_ctr = 0;
    }
}

// ---------------- last-layer BN apply + pool ----------------
__global__ void bn_pool(int n, const int* __restrict__ batch) {
    long stride = (long)gridDim.x * blockDim.x;
    long total = (long)n * Hd;
    for (long i = (long)blockIdx.x * blockDim.x + threadIdx.x; i < total; i += stride) {
        int c = (int)(i & 127);
        float v = fmaxf(g_h[i] * g_scale[c] + g_shift[c], 0.f);
        int node = (int)(i >> 7);
        atomicAdd(&g_pool[batch[node] * Hd + c], v);
    }
}

__global__ void classify(const float* __restrict__ W, const float* __restrict__ b,
                         float* __restrict__ out) {
    int g = blockIdx.x;
    int c = threadIdx.x;
    if (c >= Cc) return;
    float inv = 1.f / fmaxf(g_cnt[g], 1.f);
    float acc = 0.f;
    #pragma unroll 8
    for (int h = 0; h < Hd; h++) acc += g_pool[g * Hd + h] * W[h * Cc + c];
    out[g * Cc + c] = acc * inv + b[c];
}

// ---------------- host orchestration ----------------
extern "C" void kernel_launch(void* const* d_in, const int* in_sizes, int n_in,
                              void* d_out, int out_size)
{
    const float* x     = (const float*)d_in[0];
    const int*   ei    = (const int*)d_in[1];
    const int*   batch = (const int*)d_in[2];
    const float* Wq1 = (const float*)d_in[3];
    const float* bq1 = (const float*)d_in[4];
    const float* Wk1 = (const float*)d_in[5];
    const float* bk1 = (const float*)d_in[6];
    const float* Wv1 = (const float*)d_in[7];
    const float* bv1 = (const float*)d_in[8];
    const float* Ws1 = (const float*)d_in[9];
    const float* bs1 = (const float*)d_in[10];
    const float* bn1g = (const float*)d_in[11];
    const float* bn1b = (const float*)d_in[12];
    const float* Wq = (const float*)d_in[13];
    const float* bq = (const float*)d_in[14];
    const float* Wk = (const float*)d_in[15];
    const float* bk = (const float*)d_in[16];
    const float* Wv = (const float*)d_in[17];
    const float* bv = (const float*)d_in[18];
    const float* Ws = (const float*)d_in[19];
    const float* bs = (const float*)d_in[20];
    const float* bng = (const float*)d_in[21];
    const float* bnb = (const float*)d_in[22];
    const float* linW = (const float*)d_in[23];
    const float* linb = (const float*)d_in[24];

    int n = in_sizes[0] / IN_DIM;
    int E = in_sizes[1] / 2;
    int ntiles = (n + 127) / 128;
    const int* src = ei;
    const int* dst = ei + E;
    const int NB = 2048;

    const int SMEM64  = (128 * (IN_DIM + 8)) * 2 + 3 * 2 * BTSZ * 2;  // 18432+61440=79872
    const int SMEM128 = (128 * (Hd + 8)) * 2 + 2 * 2 * BTSZ * 2;      // 34816+40960=75776
    cudaFuncSetAttribute((const void*)gemm_mma<IN_DIM, 3, false>, cudaFuncAttributeMaxDynamicSharedMemorySize, SMEM64);
    cudaFuncSetAttribute((const void*)gemm_mma<Hd, 2, true>,      cudaFuncAttributeMaxDynamicSharedMemorySize, SMEM128);

    // #1 prep, #2 setup, #3 scan
    prep_layer1<<<1024, 256>>>(x, n, ntiles, Wq1, Wk1, Wv1, Ws1, bq1, bk1, bv1, bs1);
    setup2<<<(E + 255) / 256, 256>>>(dst, batch, n, E);
    scan_block<<<1, 1024>>>(n);
    // #4 GEMM layer 1
    gemm_mma<IN_DIM, 3, false><<<dim3(ntiles, 2), 256, SMEM64>>>(n);
    // #5 scatter
    csr_scatter<<<(E + 255) / 256, 256>>>(src, dst, E);
    // #6 attention layer 1 + BN stats + B prep for hidden layer 0
    attn_fused<<<NB + 256, 256>>>(n, NB, bn1g, bn1b, Wq, Wk, Wv, Ws, bq, bk, bv, bs);

    for (int i = 0; i < Ld; i++) {
        gemm_mma<Hd, 2, true><<<dim3(ntiles, 2), 256, SMEM128>>>(n);
        int last = (i == Ld - 1);
        const float* nWq = last ? nullptr : Wq + (size_t)(i + 1) * Hd * Hd;
        const float* nWk = last ? nullptr : Wk + (size_t)(i + 1) * Hd * Hd;
        const float* nWv = last ? nullptr : Wv + (size_t)(i + 1) * Hd * Hd;
        const float* nWs = last ? nullptr : Ws + (size_t)(i + 1) * Hd * Hd;
        const float* nbq = last ? nullptr : bq + (i + 1) * Hd;
        const float* nbk = last ? nullptr : bk + (i + 1) * Hd;
        const float* nbv = last ? nullptr : bv + (i + 1) * Hd;
        const float* nbs = last ? nullptr : bs + (i + 1) * Hd;
        attn_fused<<<NB + 256, 256>>>(n, NB, bng + i * Hd, bnb + i * Hd,
                                      nWq, nWk, nWv, nWs, nbq, nbk, nbv, nbs);
    }

    bn_pool<<<512, 256>>>(n, batch);
    classify<<<Gg, 32>>>(linW, linb, (float*)d_out);
}

// round 16
// speedup vs baseline: 1.3588x; 1.0849x over previous
#include <cuda_runtime.h>
#include <cuda_bf16.h>
#include <cuda_fp16.h>
#include <math.h>
#include <stdint.h>

// Problem constants
#define Nn 100000
#define Ee 600000
#define IN_DIM 64
#define Hd 128
#define Ld 3
#define Gg 256
#define Cc 10
#define NTILES ((Nn + 127) / 128)

// ---------------- device scratch ----------------
__device__ float  g_h[(size_t)Nn * Hd];
__device__ float  g_q[(size_t)Nn * Hd];
__device__ float  g_s[(size_t)Nn * Hd];
__device__ __align__(16) __nv_bfloat16 g_kv[(size_t)Nn * 256]; // k|v bf16
__device__ double g_sum[Hd];
__device__ double g_sumsq[Hd];
__device__ float  g_scale[Hd];
__device__ float  g_shift[Hd];
__device__ float  g_pool[Gg * Hd];
__device__ float  g_cnt[Gg];
__device__ int    g_ctr;
// CSR
__device__ int    g_deg[Nn];
__device__ int    g_off[Nn + 1];
__device__ int    g_srcSorted[Ee];
// fp16 staging: A single image (layer-1), B single image (current layer)
__device__ __align__(16) __half g_Ah[(size_t)NTILES * 128 * IN_DIM];
__device__ __align__(16) __half g_Bh[512 * 128];
__device__ float  g_bias[512];

// ---------------- asm helpers ----------------
__device__ __forceinline__ uint32_t smem_u32(const void* p) {
    uint32_t a;
    asm("{ .reg .u64 t; cvta.to.shared.u64 t, %1; cvt.u32.u64 %0, t; }" : "=r"(a) : "l"(p));
    return a;
}

__device__ __forceinline__ void mma16816h(float* d,
    uint32_t a0, uint32_t a1, uint32_t a2, uint32_t a3,
    uint32_t b0, uint32_t b1)
{
    asm volatile(
        "mma.sync.aligned.m16n8k16.row.col.f32.f16.f16.f32 "
        "{%0,%1,%2,%3}, {%4,%5,%6,%7}, {%8,%9}, {%0,%1,%2,%3};"
        : "+f"(d[0]), "+f"(d[1]), "+f"(d[2]), "+f"(d[3])
        : "r"(a0), "r"(a1), "r"(a2), "r"(a3), "r"(b0), "r"(b1));
}

__device__ __forceinline__ void ldsm4(uint32_t* r, uint32_t addr) {
    asm volatile("ldmatrix.sync.aligned.m8n8.x4.shared.b16 {%0,%1,%2,%3}, [%4];"
        : "=r"(r[0]), "=r"(r[1]), "=r"(r[2]), "=r"(r[3]) : "r"(addr));
}

#define CP_ASYNC16(dst, src) \
    asm volatile("cp.async.cg.shared.global [%0], [%1], 16;" :: "r"(dst), "l"(src))
#define CP_COMMIT()  asm volatile("cp.async.commit_group;" ::: "memory")

__device__ __forceinline__ float4 ld_bf4(const __nv_bfloat16* p) {
    uint2 u = *(const uint2*)p;
    __nv_bfloat162 a = *reinterpret_cast<__nv_bfloat162*>(&u.x);
    __nv_bfloat162 b = *reinterpret_cast<__nv_bfloat162*>(&u.y);
    float2 fa = __bfloat1622float2(a), fb = __bfloat1622float2(b);
    return make_float4(fa.x, fa.y, fb.x, fb.y);
}

// ---------------- fused layer-1 prep (+ deg zero) ----------------
__global__ void prep_layer1(const float* __restrict__ x, int n, int ntiles,
                            const float* __restrict__ Wq, const float* __restrict__ Wk,
                            const float* __restrict__ Wv, const float* __restrict__ Ws,
                            const float* __restrict__ bq, const float* __restrict__ bk,
                            const float* __restrict__ bv, const float* __restrict__ bs)
{
    long aTot = (long)ntiles * 128 * IN_DIM;
    long bTot = 512 * IN_DIM;
    long total = aTot + bTot + 512 + n;
    long stride = (long)gridDim.x * blockDim.x;
    for (long idx = (long)blockIdx.x * blockDim.x + threadIdx.x; idx < total; idx += stride) {
        if (idx < aTot) {
            long row = idx / IN_DIM;
            int  k = (int)(idx % IN_DIM);
            float v = (row < n) ? x[row * IN_DIM + k] : 0.f;
            g_Ah[idx] = __float2half(v);
        } else if (idx < aTot + bTot) {
            int j = (int)(idx - aTot);
            int nglob = j / IN_DIM, k = j % IN_DIM;
            int w = nglob >> 7, nloc = nglob & 127;
            const float* W = (w == 0) ? Wq : (w == 1) ? Wk : (w == 2) ? Wv : Ws;
            g_Bh[j] = __float2half(W[(size_t)k * Hd + nloc]);
        } else if (idx < aTot + bTot + 512) {
            int nglob = (int)(idx - aTot - bTot);
            int w = nglob >> 7, nloc = nglob & 127;
            const float* B = (w == 0) ? bq : (w == 1) ? bk : (w == 2) ? bv : bs;
            g_bias[nglob] = B[nloc];
        } else {
            g_deg[idx - aTot - bTot - 512] = 0;
        }
    }
}

// ---------------- setup2 ----------------
__global__ void setup2(const int* __restrict__ dst, const int* __restrict__ batch,
                       int n, int E) {
    int idx = blockIdx.x * blockDim.x + threadIdx.x;
    if (idx < E) atomicAdd(&g_deg[dst[idx]], 1);
    if (idx == 0) { g_off[0] = 0; g_ctr = 0; }
    if (idx < Hd) { g_sum[idx] = 0.0; g_sumsq[idx] = 0.0; }
    if (idx < Gg * Hd) g_pool[idx] = 0.f;
    if (idx < Gg) {
        int g = idx;
        int lo = 0, hi = n;
        while (lo < hi) { int mid = (lo + hi) >> 1; if (batch[mid] < g) lo = mid + 1; else hi = mid; }
        int lb = lo;
        lo = 0; hi = n;
        while (lo < hi) { int mid = (lo + hi) >> 1; if (batch[mid] <= g) lo = mid + 1; else hi = mid; }
        g_cnt[g] = (float)(lo - lb);
    }
}

__global__ void __launch_bounds__(1024) scan_block(int n) {
    __shared__ int sh[1024];
    int t = threadIdx.x;
    int chunk = (n + 1023) >> 10;
    int s0 = min(t * chunk, n), s1 = min(s0 + chunk, n);
    int s = 0;
    for (int i = s0; i < s1; i++) s += g_deg[i];
    sh[t] = s;
    __syncthreads();
    #pragma unroll
    for (int d = 1; d < 1024; d <<= 1) {
        int v = (t >= d) ? sh[t - d] : 0;
        __syncthreads();
        sh[t] += v;
        __syncthreads();
    }
    int run = (t == 0) ? 0 : sh[t - 1];
    for (int i = s0; i < s1; i++) {
        int d = g_deg[i];
        g_deg[i] = run;
        run += d;
        g_off[i + 1] = run;
    }
}

__global__ void csr_scatter(const int* __restrict__ src, const int* __restrict__ dst, int E) {
    int e = blockIdx.x * blockDim.x + threadIdx.x;
    if (e >= E) return;
    int pos = atomicAdd(&g_deg[dst[e]], 1);
    g_srcSorted[pos] = src[e];
}

// ---------------- GEMM: pure fp16, 1 MMA per tile ----------------
#define BSTR 40
#define BTSZ (128 * BSTR)

template<int K, int S, bool FUSE>
__global__ void __launch_bounds__(256, 2) gemm_mma(int n) {
    constexpr int ASTR = K + 8;
    constexpr int ATSZ = 128 * ASTR;        // single A image
    constexpr int NK = K / 32;
    constexpr int P = 2 * NK;
    extern __shared__ __half sm[];
    const int B_OFF = ATSZ;

    const int tid = threadIdx.x;
    const int tile = blockIdx.x;
    const int cb = blockIdx.y * 2;
    const int wid = tid >> 5, lane = tid & 31;
    const int wm = (wid & 3) * 32, wn = (wid >> 2) * 64;
    const int gid = lane >> 2, tig = lane & 3;
    const uint32_t smb = smem_u32(sm);

    auto stageB = [&](int pp) {
        int buf = pp % S;
        int cc = cb + pp / NK;
        int kt = (pp % NK) * 32;
        #pragma unroll
        for (int t = 0; t < 2; t++) {
            int idx = tid + t * 256;            // 512 chunks of 16B
            int r = idx >> 2, c = idx & 3;
            const __half* sp = g_Bh + (size_t)(cc * 128 + r) * K + kt + c * 8;
            uint32_t d = smb + (uint32_t)(B_OFF + buf * BTSZ + r * BSTR + c * 8) * 2;
            CP_ASYNC16(d, sp);
        }
        CP_COMMIT();
    };

    if (FUSE) {
        #pragma unroll
        for (int s = 0; s < S - 1; s++) stageB(s);
        const int cg = (tid & 31) * 4;
        const float4 sc4 = *(const float4*)(g_scale + cg);
        const float4 sh4 = *(const float4*)(g_shift + cg);
        #pragma unroll
        for (int t = 0; t < 16; t++) {
            int idx = tid + t * 256;
            int r = idx >> 5;
            long grow = (long)tile * 128 + r;
            float4 v = make_float4(0.f, 0.f, 0.f, 0.f);
            if (grow < n) v = *(const float4*)(g_h + grow * 128 + cg);
            v.x = fmaxf(v.x * sc4.x + sh4.x, 0.f);
            v.y = fmaxf(v.y * sc4.y + sh4.y, 0.f);
            v.z = fmaxf(v.z * sc4.z + sh4.z, 0.f);
            v.w = fmaxf(v.w * sc4.w + sh4.w, 0.f);
            __half2 h0 = __floats2half2_rn(v.x, v.y);
            __half2 h1 = __floats2half2_rn(v.z, v.w);
            uint2 uh;
            uh.x = *(uint32_t*)&h0; uh.y = *(uint32_t*)&h1;
            *(uint2*)&sm[r * ASTR + cg] = uh;
        }
    } else {
        const __half* aP = g_Ah + (size_t)tile * 128 * K;
        constexpr int ACH = 128 * (K / 8);
        #pragma unroll
        for (int t = 0; t < ACH / 256; t++) {
            int i = tid + t * 256;
            int r = i / (K / 8), c = i % (K / 8);
            const __half* sp = aP + (size_t)r * K + c * 8;
            uint32_t d = smb + (uint32_t)(r * ASTR + c * 8) * 2;
            CP_ASYNC16(d, sp);
        }
        #pragma unroll
        for (int s = 0; s < S - 1; s++) stageB(s);
    }

    float acc[2][8][4] = {};

    #pragma unroll 1
    for (int p = 0; p < P; p++) {
        if (p + S - 1 < P) {
            stageB(p + S - 1);
            asm volatile("cp.async.wait_group %0;" :: "n"(S - 1) : "memory");
        } else {
            asm volatile("cp.async.wait_group 0;" ::: "memory");
        }
        __syncthreads();

        const int ktA = (p % NK) * 32;
        const uint32_t bbase = smb + (uint32_t)(B_OFF + (p % S) * BTSZ) * 2;

        #pragma unroll
        for (int ks = 0; ks < 2; ks++) {
            const int kb = ks * 16;
            uint32_t ah[2][4];
            #pragma unroll
            for (int mt = 0; mt < 2; mt++) {
                int row = wm + mt * 16 + (lane & 15);
                int col = ktA + kb + ((lane & 16) ? 8 : 0);
                uint32_t ad = smb + (uint32_t)(row * ASTR + col) * 2;
                ldsm4(ah[mt], ad);
            }
            #pragma unroll
            for (int ntp = 0; ntp < 4; ntp++) {
                int row = wn + ntp * 16 + (lane & 7) + ((lane & 16) ? 8 : 0);
                int col = kb + ((lane & 8) ? 8 : 0);
                uint32_t bd = bbase + (uint32_t)(row * BSTR + col) * 2;
                uint32_t bh[4];
                ldsm4(bh, bd);
                #pragma unroll
                for (int sub = 0; sub < 2; sub++) {
                    int nt = ntp * 2 + sub;
                    #pragma unroll
                    for (int mt = 0; mt < 2; mt++) {
                        mma16816h(acc[mt][nt], ah[mt][0], ah[mt][1], ah[mt][2], ah[mt][3], bh[sub*2], bh[sub*2+1]);
                    }
                }
            }
        }
        __syncthreads();

        if ((p % NK) == NK - 1) {
            const int cc = cb + p / NK;
            #pragma unroll
            for (int mt = 0; mt < 2; mt++) {
                long r0 = (long)tile * 128 + wm + mt * 16 + gid;
                #pragma unroll
                for (int nt = 0; nt < 8; nt++) {
                    int col = wn + nt * 8 + tig * 2;
                    float b0 = g_bias[cc * 128 + col], b1 = g_bias[cc * 128 + col + 1];
                    float v0 = acc[mt][nt][0] + b0, v1 = acc[mt][nt][1] + b1;
                    float v2 = acc[mt][nt][2] + b0, v3 = acc[mt][nt][3] + b1;
                    if (cc == 0) {
                        if (r0 < n)     *(float2*)(g_q + r0 * 128 + col)       = make_float2(v0, v1);
                        if (r0 + 8 < n) *(float2*)(g_q + (r0 + 8) * 128 + col) = make_float2(v2, v3);
                    } else if (cc == 3) {
                        if (r0 < n)     *(float2*)(g_s + r0 * 128 + col)       = make_float2(v0, v1);
                        if (r0 + 8 < n) *(float2*)(g_s + (r0 + 8) * 128 + col) = make_float2(v2, v3);
                    } else {
                        int off = (cc == 2) ? 128 : 0;
                        __nv_bfloat162 p0 = __floats2bfloat162_rn(v0, v1);
                        __nv_bfloat162 p1 = __floats2bfloat162_rn(v2, v3);
                        if (r0 < n)     *(__nv_bfloat162*)(g_kv + r0 * 256 + off + col)       = p0;
                        if (r0 + 8 < n) *(__nv_bfloat162*)(g_kv + (r0 + 8) * 256 + off + col) = p1;
                    }
                    acc[mt][nt][0] = 0.f; acc[mt][nt][1] = 0.f;
                    acc[mt][nt][2] = 0.f; acc[mt][nt][3] = 0.f;
                }
            }
        }
    }
}

// ---------------- attention (R14 winner) + BN stats + next-layer B prep ----------------
__global__ void __launch_bounds__(256) attn_fused(int n, int NB,
        const float* __restrict__ gamma, const float* __restrict__ beta,
        const float* __restrict__ Wq, const float* __restrict__ Wk,
        const float* __restrict__ Wv, const float* __restrict__ Ws,
        const float* __restrict__ bq, const float* __restrict__ bk,
        const float* __restrict__ bv, const float* __restrict__ bs) {
    if ((int)blockIdx.x >= NB) {
        if (Wq) {
            int idx = ((int)blockIdx.x - NB) * 256 + threadIdx.x;
            int nglob = idx / Hd, k = idx % Hd;
            int w = nglob >> 7, nloc = nglob & 127;
            const float* W = (w == 0) ? Wq : (w == 1) ? Wk : (w == 2) ? Wv : Ws;
            g_Bh[idx] = __float2half(W[(size_t)k * Hd + nloc]);
            if (k == 0) {
                const float* B = (w == 0) ? bq : (w == 1) ? bk : (w == 2) ? bv : bs;
                g_bias[nglob] = B[nloc];
            }
        }
        return;
    }

    __shared__ float ssum[Hd], ssq[Hd];
    __shared__ int sh_last;
    for (int i = threadIdx.x; i < Hd; i += 256) { ssum[i] = 0.f; ssq[i] = 0.f; }
    __syncthreads();

    const int lane = threadIdx.x & 31;
    const int c0 = lane * 4;
    const int wstride = NB * 8;
    const float SCALE = 0.08838834764831845f;
    float ls0 = 0.f, ls1 = 0.f, ls2 = 0.f, ls3 = 0.f;
    float lq0 = 0.f, lq1 = 0.f, lq2 = 0.f, lq3 = 0.f;

    for (int node = blockIdx.x * 8 + (threadIdx.x >> 5); node < n; node += wstride) {
        const int off0 = g_off[node];
        const int deg  = g_off[node + 1] - off0;
        const float4 q = *(const float4*)(g_q + (size_t)node * 128 + c0);

        float sum = 0.f;
        float ax = 0.f, ay = 0.f, az = 0.f, aw = 0.f;

        for (int base = 0; base < deg; base += 32) {
            const int c = min(32, deg - base);
            int myidx = (lane < c) ? g_srcSorted[off0 + base + lane] : 0;

            #pragma unroll 4
            for (int j = 0; j < c; j++) {
                int s = __shfl_sync(0xffffffffu, myidx, j);
                const __nv_bfloat16* row = g_kv + (size_t)s * 256;
                float4 kk = ld_bf4(row + c0);
                float4 vv = ld_bf4(row + 128 + c0);
                float p = q.x * kk.x + q.y * kk.y + q.z * kk.z + q.w * kk.w;
                #pragma unroll
                for (int o = 16; o; o >>= 1) p += __shfl_xor_sync(0xffffffffu, p, o);
                float w = __expf(p * SCALE);
                ax += w * vv.x;
                ay += w * vv.y;
                az += w * vv.z;
                aw += w * vv.w;
                sum += w;
            }
        }

        float inv = (deg > 0) ? 1.f / sum : 0.f;
        float4 sk = *(const float4*)(g_s + (size_t)node * 128 + c0);
        float h0 = ax * inv + sk.x;
        float h1 = ay * inv + sk.y;
        float h2 = az * inv + sk.z;
        float h3 = aw * inv + sk.w;
        *(float4*)(g_h + (size_t)node * Hd + c0) = make_float4(h0, h1, h2, h3);
        ls0 += h0; ls1 += h1; ls2 += h2; ls3 += h3;
        lq0 += h0 * h0; lq1 += h1 * h1; lq2 += h2 * h2; lq3 += h3 * h3;
    }

    atomicAdd(&ssum[c0 + 0], ls0); atomicAdd(&ssq[c0 + 0], lq0);
    atomicAdd(&ssum[c0 + 1], ls1); atomicAdd(&ssq[c0 + 1], lq1);
    atomicAdd(&ssum[c0 + 2], ls2); atomicAdd(&ssq[c0 + 2], lq2);
    atomicAdd(&ssum[c0 + 3], ls3); atomicAdd(&ssq[c0 + 3], lq3);
    __syncthreads();
    if (threadIdx.x < Hd) {
        atomicAdd(&g_sum[threadIdx.x], (double)ssum[threadIdx.x]);
        atomicAdd(&g_sumsq[threadIdx.x], (double)ssq[threadIdx.x]);
    }

    __threadfence();
    if (threadIdx.x == 0) {
        int t = atomicAdd(&g_ctr, 1);
        sh_last = (t == NB - 1);
    }
    __syncthreads();
    if (sh_last) {
        int ch = threadIdx.x;
        if (ch < Hd) {
            double mean = g_sum[ch] / n;
            double var  = g_sumsq[ch] / n - mean * mean;
            if (var < 0.0) var = 0.0;
            float invs = (float)rsqrt(var + 1e-5);
            float scv = invs * gamma[ch];
            g_scale[ch] = scv;
            g_shift[ch] = beta[ch] - (float)mean * scv;
            g_sum[ch] = 0.0;
            g_sumsq[ch] = 0.0;
        }
        if (threadIdx.x == 0) g_ctr = 0;
    }
}

// ---------------- last-layer BN apply + pool ----------------
__global__ void bn_pool(int n, const int* __restrict__ batch) {
    long stride = (long)gridDim.x * blockDim.x;
    long total = (long)n * Hd;
    for (long i = (long)blockIdx.x * blockDim.x + threadIdx.x; i < total; i += stride) {
        int c = (int)(i & 127);
        float v = fmaxf(g_h[i] * g_scale[c] + g_shift[c], 0.f);
        int node = (int)(i >> 7);
        atomicAdd(&g_pool[batch[node] * Hd + c], v);
    }
}

__global__ void classify(const float* __restrict__ W, const float* __restrict__ b,
                         float* __restrict__ out) {
    int g = blockIdx.x;
    int c = threadIdx.x;
    if (c >= Cc) return;
    float inv = 1.f / fmaxf(g_cnt[g], 1.f);
    float acc = 0.f;
    #pragma unroll 8
    for (int h = 0; h < Hd; h++) acc += g_pool[g * Hd + h] * W[h * Cc + c];
    out[g * Cc + c] = acc * inv + b[c];
}

// ---------------- host orchestration ----------------
extern "C" void kernel_launch(void* const* d_in, const int* in_sizes, int n_in,
                              void* d_out, int out_size)
{
    const float* x     = (const float*)d_in[0];
    const int*   ei    = (const int*)d_in[1];
    const int*   batch = (const int*)d_in[2];
    const float* Wq1 = (const float*)d_in[3];
    const float* bq1 = (const float*)d_in[4];
    const float* Wk1 = (const float*)d_in[5];
    const float* bk1 = (const float*)d_in[6];
    const float* Wv1 = (const float*)d_in[7];
    const float* bv1 = (const float*)d_in[8];
    const float* Ws1 = (const float*)d_in[9];
    const float* bs1 = (const float*)d_in[10];
    const float* bn1g = (const float*)d_in[11];
    const float* bn1b = (const float*)d_in[12];
    const float* Wq = (const float*)d_in[13];
    const float* bq = (const float*)d_in[14];
    const float* Wk = (const float*)d_in[15];
    const float* bk = (const float*)d_in[16];
    const float* Wv = (const float*)d_in[17];
    const float* bv = (const float*)d_in[18];
    const float* Ws = (const float*)d_in[19];
    const float* bs = (const float*)d_in[20];
    const float* bng = (const float*)d_in[21];
    const float* bnb = (const float*)d_in[22];
    const float* linW = (const float*)d_in[23];
    const float* linb = (const float*)d_in[24];

    int n = in_sizes[0] / IN_DIM;
    int E = in_sizes[1] / 2;
    int ntiles = (n + 127) / 128;
    const int* src = ei;
    const int* dst = ei + E;
    const int NB = 2048;

    const int SMEM64  = (128 * (IN_DIM + 8)) * 2 + 3 * BTSZ * 2;  // 18432+30720=49152
    const int SMEM128 = (128 * (Hd + 8)) * 2 + 2 * BTSZ * 2;      // 34816+20480=55296
    cudaFuncSetAttribute((const void*)gemm_mma<IN_DIM, 3, false>, cudaFuncAttributeMaxDynamicSharedMemorySize, SMEM64);
    cudaFuncSetAttribute((const void*)gemm_mma<Hd, 2, true>,      cudaFuncAttributeMaxDynamicSharedMemorySize, SMEM128);

    // #1 prep, #2 setup, #3 scan
    prep_layer1<<<1024, 256>>>(x, n, ntiles, Wq1, Wk1, Wv1, Ws1, bq1, bk1, bv1, bs1);
    setup2<<<(E + 255) / 256, 256>>>(dst, batch, n, E);
    scan_block<<<1, 1024>>>(n);
    // #4 GEMM layer 1
    gemm_mma<IN_DIM, 3, false><<<dim3(ntiles, 2), 256, SMEM64>>>(n);
    // #5 scatter
    csr_scatter<<<(E + 255) / 256, 256>>>(src, dst, E);
    // #6 attention layer 1 + BN stats + B prep for hidden layer 0
    attn_fused<<<NB + 256, 256>>>(n, NB, bn1g, bn1b, Wq, Wk, Wv, Ws, bq, bk, bv, bs);

    for (int i = 0; i < Ld; i++) {
        gemm_mma<Hd, 2, true><<<dim3(ntiles, 2), 256, SMEM128>>>(n);
        int last = (i == Ld - 1);
        const float* nWq = last ? nullptr : Wq + (size_t)(i + 1) * Hd * Hd;
        const float* nWk = last ? nullptr : Wk + (size_t)(i + 1) * Hd * Hd;
        const float* nWv = last ? nullptr : Wv + (size_t)(i + 1) * Hd * Hd;
        const float* nWs = last ? nullptr : Ws + (size_t)(i + 1) * Hd * Hd;
        const float* nbq = last ? nullptr : bq + (i + 1) * Hd;
        const float* nbk = last ? nullptr : bk + (i + 1) * Hd;
        const float* nbv = last ? nullptr : bv + (i + 1) * Hd;
        const float* nbs = last ? nullptr : bs + (i + 1) * Hd;
        attn_fused<<<NB + 256, 256>>>(n, NB, bng + i * Hd, bnb + i * Hd,
                                      nWq, nWk, nWv, nWs, nbq, nbk, nbv, nbs);
    }

    bn_pool<<<512, 256>>>(n, batch);
    classify<<<Gg, 32>>>(linW, linb, (float*)d_out);
}

// round 17
// speedup vs baseline: 1.3697x; 1.0080x over previous
#include <cuda_runtime.h>
#include <cuda_bf16.h>
#include <cuda_fp16.h>
#include <math.h>
#include <stdint.h>

// Problem constants
#define Nn 100000
#define Ee 600000
#define IN_DIM 64
#define Hd 128
#define Ld 3
#define Gg 256
#define Cc 10
#define NTILES ((Nn + 127) / 128)

// ---------------- device scratch ----------------
__device__ float  g_h[(size_t)Nn * Hd];
__device__ float  g_q[(size_t)Nn * Hd];
__device__ float  g_s[(size_t)Nn * Hd];
__device__ __align__(16) __nv_bfloat16 g_kv[(size_t)Nn * 256]; // k|v bf16
__device__ double g_sum[Hd];
__device__ double g_sumsq[Hd];
__device__ float  g_scale[Hd];
__device__ float  g_shift[Hd];
__device__ float  g_pool[Gg * Hd];
__device__ float  g_cnt[Gg];
__device__ int    g_ctr;
// CSR
__device__ int    g_deg[Nn];
__device__ int    g_off[Nn + 1];
__device__ int    g_srcSorted[Ee];
// fp16 staging
__device__ __align__(16) __half g_Ah[(size_t)NTILES * 128 * IN_DIM];
__device__ __align__(16) __half g_Bh[512 * 128];
__device__ float  g_bias[512];

// ---------------- asm helpers ----------------
__device__ __forceinline__ uint32_t smem_u32(const void* p) {
    uint32_t a;
    asm("{ .reg .u64 t; cvta.to.shared.u64 t, %1; cvt.u32.u64 %0, t; }" : "=r"(a) : "l"(p));
    return a;
}

__device__ __forceinline__ void mma16816h(float* d,
    uint32_t a0, uint32_t a1, uint32_t a2, uint32_t a3,
    uint32_t b0, uint32_t b1)
{
    asm volatile(
        "mma.sync.aligned.m16n8k16.row.col.f32.f16.f16.f32 "
        "{%0,%1,%2,%3}, {%4,%5,%6,%7}, {%8,%9}, {%0,%1,%2,%3};"
        : "+f"(d[0]), "+f"(d[1]), "+f"(d[2]), "+f"(d[3])
        : "r"(a0), "r"(a1), "r"(a2), "r"(a3), "r"(b0), "r"(b1));
}

__device__ __forceinline__ void ldsm4(uint32_t* r, uint32_t addr) {
    asm volatile("ldmatrix.sync.aligned.m8n8.x4.shared.b16 {%0,%1,%2,%3}, [%4];"
        : "=r"(r[0]), "=r"(r[1]), "=r"(r[2]), "=r"(r[3]) : "r"(addr));
}

#define CP_ASYNC16(dst, src) \
    asm volatile("cp.async.cg.shared.global [%0], [%1], 16;" :: "r"(dst), "l"(src))
#define CP_COMMIT()  asm volatile("cp.async.commit_group;" ::: "memory")

__device__ __forceinline__ float4 ld_bf4(const __nv_bfloat16* p) {
    uint2 u = *(const uint2*)p;
    __nv_bfloat162 a = *reinterpret_cast<__nv_bfloat162*>(&u.x);
    __nv_bfloat162 b = *reinterpret_cast<__nv_bfloat162*>(&u.y);
    float2 fa = __bfloat1622float2(a), fb = __bfloat1622float2(b);
    return make_float4(fa.x, fa.y, fb.x, fb.y);
}

// ---------------- fused layer-1 prep (+ deg zero) ----------------
__global__ void prep_layer1(const float* __restrict__ x, int n, int ntiles,
                            const float* __restrict__ Wq, const float* __restrict__ Wk,
                            const float* __restrict__ Wv, const float* __restrict__ Ws,
                            const float* __restrict__ bq, const float* __restrict__ bk,
                            const float* __restrict__ bv, const float* __restrict__ bs)
{
    long aTot = (long)ntiles * 128 * IN_DIM;
    long bTot = 512 * IN_DIM;
    long total = aTot + bTot + 512 + n;
    long stride = (long)gridDim.x * blockDim.x;
    for (long idx = (long)blockIdx.x * blockDim.x + threadIdx.x; idx < total; idx += stride) {
        if (idx < aTot) {
            long row = idx / IN_DIM;
            int  k = (int)(idx % IN_DIM);
            float v = (row < n) ? x[row * IN_DIM + k] : 0.f;
            g_Ah[idx] = __float2half(v);
        } else if (idx < aTot + bTot) {
            int j = (int)(idx - aTot);
            int nglob = j / IN_DIM, k = j % IN_DIM;
            int w = nglob >> 7, nloc = nglob & 127;
            const float* W = (w == 0) ? Wq : (w == 1) ? Wk : (w == 2) ? Wv : Ws;
            g_Bh[j] = __float2half(W[(size_t)k * Hd + nloc]);
        } else if (idx < aTot + bTot + 512) {
            int nglob = (int)(idx - aTot - bTot);
            int w = nglob >> 7, nloc = nglob & 127;
            const float* B = (w == 0) ? bq : (w == 1) ? bk : (w == 2) ? bv : bs;
            g_bias[nglob] = B[nloc];
        } else {
            g_deg[idx - aTot - bTot - 512] = 0;
        }
    }
}

// ---------------- setup2 ----------------
__global__ void setup2(const int* __restrict__ dst, const int* __restrict__ batch,
                       int n, int E) {
    int idx = blockIdx.x * blockDim.x + threadIdx.x;
    if (idx < E) atomicAdd(&g_deg[dst[idx]], 1);
    if (idx == 0) { g_off[0] = 0; g_ctr = 0; }
    if (idx < Hd) { g_sum[idx] = 0.0; g_sumsq[idx] = 0.0; }
    if (idx < Gg * Hd) g_pool[idx] = 0.f;
    if (idx < Gg) {
        int g = idx;
        int lo = 0, hi = n;
        while (lo < hi) { int mid = (lo + hi) >> 1; if (batch[mid] < g) lo = mid + 1; else hi = mid; }
        int lb = lo;
        lo = 0; hi = n;
        while (lo < hi) { int mid = (lo + hi) >> 1; if (batch[mid] <= g) lo = mid + 1; else hi = mid; }
        g_cnt[g] = (float)(lo - lb);
    }
}

__global__ void __launch_bounds__(1024) scan_block(int n) {
    __shared__ int sh[1024];
    int t = threadIdx.x;
    int chunk = (n + 1023) >> 10;
    int s0 = min(t * chunk, n), s1 = min(s0 + chunk, n);
    int s = 0;
    for (int i = s0; i < s1; i++) s += g_deg[i];
    sh[t] = s;
    __syncthreads();
    #pragma unroll
    for (int d = 1; d < 1024; d <<= 1) {
        int v = (t >= d) ? sh[t - d] : 0;
        __syncthreads();
        sh[t] += v;
        __syncthreads();
    }
    int run = (t == 0) ? 0 : sh[t - 1];
    for (int i = s0; i < s1; i++) {
        int d = g_deg[i];
        g_deg[i] = run;
        run += d;
        g_off[i + 1] = run;
    }
}

__global__ void csr_scatter(const int* __restrict__ src, const int* __restrict__ dst, int E) {
    int e = blockIdx.x * blockDim.x + threadIdx.x;
    if (e >= E) return;
    int pos = atomicAdd(&g_deg[dst[e]], 1);
    g_srcSorted[pos] = src[e];
}

// ---------------- GEMM: pure fp16, 64-wide k-stages ----------------
#define BSTR 72                  // 64 data + 8 pad
#define BTSZ (128 * BSTR)

template<int K, bool FUSE>
__global__ void __launch_bounds__(256, 2) gemm_mma(int n) {
    constexpr int ASTR = K + 8;
    constexpr int ATSZ = 128 * ASTR;
    constexpr int NK = K / 64;          // k-stages per chunk
    constexpr int P = 2 * NK;           // 2 chunks per CTA
    extern __shared__ __half sm[];
    const int B_OFF = ATSZ;

    const int tid = threadIdx.x;
    const int tile = blockIdx.x;
    const int cb = blockIdx.y * 2;
    const int wid = tid >> 5, lane = tid & 31;
    const int wm = (wid & 3) * 32, wn = (wid >> 2) * 64;
    const int gid = lane >> 2, tig = lane & 3;
    const uint32_t smb = smem_u32(sm);

    auto stageB = [&](int pp) {
        int buf = pp & 1;
        int cc = cb + pp / NK;
        int kt = (pp % NK) * 64;
        #pragma unroll
        for (int t = 0; t < 4; t++) {
            int idx = tid + t * 256;            // 1024 chunks of 16B
            int r = idx >> 3, c = idx & 7;
            const __half* sp = g_Bh + (size_t)(cc * 128 + r) * K + kt + c * 8;
            uint32_t d = smb + (uint32_t)(B_OFF + buf * BTSZ + r * BSTR + c * 8) * 2;
            CP_ASYNC16(d, sp);
        }
        CP_COMMIT();
    };

    if (FUSE) {
        stageB(0);
        const int cg = (tid & 31) * 4;
        const float4 sc4 = *(const float4*)(g_scale + cg);
        const float4 sh4 = *(const float4*)(g_shift + cg);
        #pragma unroll
        for (int t = 0; t < 16; t++) {
            int idx = tid + t * 256;
            int r = idx >> 5;
            long grow = (long)tile * 128 + r;
            float4 v = make_float4(0.f, 0.f, 0.f, 0.f);
            if (grow < n) v = *(const float4*)(g_h + grow * 128 + cg);
            v.x = fmaxf(v.x * sc4.x + sh4.x, 0.f);
            v.y = fmaxf(v.y * sc4.y + sh4.y, 0.f);
            v.z = fmaxf(v.z * sc4.z + sh4.z, 0.f);
            v.w = fmaxf(v.w * sc4.w + sh4.w, 0.f);
            __half2 h0 = __floats2half2_rn(v.x, v.y);
            __half2 h1 = __floats2half2_rn(v.z, v.w);
            uint2 uh;
            uh.x = *(uint32_t*)&h0; uh.y = *(uint32_t*)&h1;
            *(uint2*)&sm[r * ASTR + cg] = uh;
        }
    } else {
        const __half* aP = g_Ah + (size_t)tile * 128 * K;
        constexpr int ACH = 128 * (K / 8);
        #pragma unroll
        for (int t = 0; t < ACH / 256; t++) {
            int i = tid + t * 256;
            int r = i / (K / 8), c = i % (K / 8);
            const __half* sp = aP + (size_t)r * K + c * 8;
            uint32_t d = smb + (uint32_t)(r * ASTR + c * 8) * 2;
            CP_ASYNC16(d, sp);
        }
        stageB(0);
    }

    float acc[2][8][4] = {};

    #pragma unroll 1
    for (int p = 0; p < P; p++) {
        if (p + 1 < P) {
            stageB(p + 1);
            asm volatile("cp.async.wait_group 1;" ::: "memory");
        } else {
            asm volatile("cp.async.wait_group 0;" ::: "memory");
        }
        __syncthreads();

        const int ktA = (p % NK) * 64;
        const uint32_t bbase = smb + (uint32_t)(B_OFF + (p & 1) * BTSZ) * 2;

        #pragma unroll
        for (int ks = 0; ks < 4; ks++) {
            const int kb = ks * 16;
            uint32_t ah[2][4];
            #pragma unroll
            for (int mt = 0; mt < 2; mt++) {
                int row = wm + mt * 16 + (lane & 15);
                int col = ktA + kb + ((lane & 16) ? 8 : 0);
                uint32_t ad = smb + (uint32_t)(row * ASTR + col) * 2;
                ldsm4(ah[mt], ad);
            }
            #pragma unroll
            for (int ntp = 0; ntp < 4; ntp++) {
                int row = wn + ntp * 16 + (lane & 7) + ((lane & 16) ? 8 : 0);
                int col = kb + ((lane & 8) ? 8 : 0);
                uint32_t bd = bbase + (uint32_t)(row * BSTR + col) * 2;
                uint32_t bh[4];
                ldsm4(bh, bd);
                #pragma unroll
                for (int sub = 0; sub < 2; sub++) {
                    int nt = ntp * 2 + sub;
                    #pragma unroll
                    for (int mt = 0; mt < 2; mt++) {
                        mma16816h(acc[mt][nt], ah[mt][0], ah[mt][1], ah[mt][2], ah[mt][3], bh[sub*2], bh[sub*2+1]);
                    }
                }
            }
        }
        __syncthreads();

        if ((p % NK) == NK - 1) {
            const int cc = cb + p / NK;
            #pragma unroll
            for (int mt = 0; mt < 2; mt++) {
                long r0 = (long)tile * 128 + wm + mt * 16 + gid;
                #pragma unroll
                for (int nt = 0; nt < 8; nt++) {
                    int col = wn + nt * 8 + tig * 2;
                    float b0 = g_bias[cc * 128 + col], b1 = g_bias[cc * 128 + col + 1];
                    float v0 = acc[mt][nt][0] + b0, v1 = acc[mt][nt][1] + b1;
                    float v2 = acc[mt][nt][2] + b0, v3 = acc[mt][nt][3] + b1;
                    if (cc == 0) {
                        if (r0 < n)     *(float2*)(g_q + r0 * 128 + col)       = make_float2(v0, v1);
                        if (r0 + 8 < n) *(float2*)(g_q + (r0 + 8) * 128 + col) = make_float2(v2, v3);
                    } else if (cc == 3) {
                        if (r0 < n)     *(float2*)(g_s + r0 * 128 + col)       = make_float2(v0, v1);
                        if (r0 + 8 < n) *(float2*)(g_s + (r0 + 8) * 128 + col) = make_float2(v2, v3);
                    } else {
                        int off = (cc == 2) ? 128 : 0;
                        __nv_bfloat162 p0 = __floats2bfloat162_rn(v0, v1);
                        __nv_bfloat162 p1 = __floats2bfloat162_rn(v2, v3);
                        if (r0 < n)     *(__nv_bfloat162*)(g_kv + r0 * 256 + off + col)       = p0;
                        if (r0 + 8 < n) *(__nv_bfloat162*)(g_kv + (r0 + 8) * 256 + off + col) = p1;
                    }
                    acc[mt][nt][0] = 0.f; acc[mt][nt][1] = 0.f;
                    acc[mt][nt][2] = 0.f; acc[mt][nt][3] = 0.f;
                }
            }
        }
    }
}

// ---------------- attention (R14 winner) + BN stats + next-layer B prep ----------------
__global__ void __launch_bounds__(256) attn_fused(int n, int NB,
        const float* __restrict__ gamma, const float* __restrict__ beta,
        const float* __restrict__ Wq, const float* __restrict__ Wk,
        const float* __restrict__ Wv, const float* __restrict__ Ws,
        const float* __restrict__ bq, const float* __restrict__ bk,
        const float* __restrict__ bv, const float* __restrict__ bs) {
    if ((int)blockIdx.x >= NB) {
        if (Wq) {
            int idx = ((int)blockIdx.x - NB) * 256 + threadIdx.x;
            int nglob = idx / Hd, k = idx % Hd;
            int w = nglob >> 7, nloc = nglob & 127;
            const float* W = (w == 0) ? Wq : (w == 1) ? Wk : (w == 2) ? Wv : Ws;
            g_Bh[idx] = __float2half(W[(size_t)k * Hd + nloc]);
            if (k == 0) {
                const float* B = (w == 0) ? bq : (w == 1) ? bk : (w == 2) ? bv : bs;
                g_bias[nglob] = B[nloc];
            }
        }
        return;
    }

    __shared__ float ssum[Hd], ssq[Hd];
    __shared__ int sh_last;
    for (int i = threadIdx.x; i < Hd; i += 256) { ssum[i] = 0.f; ssq[i] = 0.f; }
    __syncthreads();

    const int lane = threadIdx.x & 31;
    const int c0 = lane * 4;
    const int wstride = NB * 8;
    const float SCALE = 0.08838834764831845f;
    float ls0 = 0.f, ls1 = 0.f, ls2 = 0.f, ls3 = 0.f;
    float lq0 = 0.f, lq1 = 0.f, lq2 = 0.f, lq3 = 0.f;

    for (int node = blockIdx.x * 8 + (threadIdx.x >> 5); node < n; node += wstride) {
        const int off0 = g_off[node];
        const int deg  = g_off[node + 1] - off0;
        const float4 q = *(const float4*)(g_q + (size_t)node * 128 + c0);

        float sum = 0.f;
        float ax = 0.f, ay = 0.f, az = 0.f, aw = 0.f;

        for (int base = 0; base < deg; base += 32) {
            const int c = min(32, deg - base);
            int myidx = (lane < c) ? g_srcSorted[off0 + base + lane] : 0;

            #pragma unroll 4
            for (int j = 0; j < c; j++) {
                int s = __shfl_sync(0xffffffffu, myidx, j);
                const __nv_bfloat16* row = g_kv + (size_t)s * 256;
                float4 kk = ld_bf4(row + c0);
                float4 vv = ld_bf4(row + 128 + c0);
                float p = q.x * kk.x + q.y * kk.y + q.z * kk.z + q.w * kk.w;
                #pragma unroll
                for (int o = 16; o; o >>= 1) p += __shfl_xor_sync(0xffffffffu, p, o);
                float w = __expf(p * SCALE);
                ax += w * vv.x;
                ay += w * vv.y;
                az += w * vv.z;
                aw += w * vv.w;
                sum += w;
            }
        }

        float inv = (deg > 0) ? 1.f / sum : 0.f;
        float4 sk = *(const float4*)(g_s + (size_t)node * 128 + c0);
        float h0 = ax * inv + sk.x;
        float h1 = ay * inv + sk.y;
        float h2 = az * inv + sk.z;
        float h3 = aw * inv + sk.w;
        *(float4*)(g_h + (size_t)node * Hd + c0) = make_float4(h0, h1, h2, h3);
        ls0 += h0; ls1 += h1; ls2 += h2; ls3 += h3;
        lq0 += h0 * h0; lq1 += h1 * h1; lq2 += h2 * h2; lq3 += h3 * h3;
    }

    atomicAdd(&ssum[c0 + 0], ls0); atomicAdd(&ssq[c0 + 0], lq0);
    atomicAdd(&ssum[c0 + 1], ls1); atomicAdd(&ssq[c0 + 1], lq1);
    atomicAdd(&ssum[c0 + 2], ls2); atomicAdd(&ssq[c0 + 2], lq2);
    atomicAdd(&ssum[c0 + 3], ls3); atomicAdd(&ssq[c0 + 3], lq3);
    __syncthreads();
    if (threadIdx.x < Hd) {
        atomicAdd(&g_sum[threadIdx.x], (double)ssum[threadIdx.x]);
        atomicAdd(&g_sumsq[threadIdx.x], (double)ssq[threadIdx.x]);
    }

    __threadfence();
    if (threadIdx.x == 0) {
        int t = atomicAdd(&g_ctr, 1);
        sh_last = (t == NB - 1);
    }
    __syncthreads();
    if (sh_last) {
        int ch = threadIdx.x;
        if (ch < Hd) {
            double mean = g_sum[ch] / n;
            double var  = g_sumsq[ch] / n - mean * mean;
            if (var < 0.0) var = 0.0;
            float invs = (float)rsqrt(var + 1e-5);
            float scv = invs * gamma[ch];
            g_scale[ch] = scv;
            g_shift[ch] = beta[ch] - (float)mean * scv;
            g_sum[ch] = 0.0;
            g_sumsq[ch] = 0.0;
        }
        if (threadIdx.x == 0) g_ctr = 0;
    }
}

// ---------------- last-layer BN apply + pool ----------------
__global__ void bn_pool(int n, const int* __restrict__ batch) {
    long stride = (long)gridDim.x * blockDim.x;
    long total = (long)n * Hd;
    for (long i = (long)blockIdx.x * blockDim.x + threadIdx.x; i < total; i += stride) {
        int c = (int)(i & 127);
        float v = fmaxf(g_h[i] * g_scale[c] + g_shift[c], 0.f);
        int node = (int)(i >> 7);
        atomicAdd(&g_pool[batch[node] * Hd + c], v);
    }
}

__global__ void classify(const float* __restrict__ W, const float* __restrict__ b,
                         float* __restrict__ out) {
    int g = blockIdx.x;
    int c = threadIdx.x;
    if (c >= Cc) return;
    float inv = 1.f / fmaxf(g_cnt[g], 1.f);
    float acc = 0.f;
    #pragma unroll 8
    for (int h = 0; h < Hd; h++) acc += g_pool[g * Hd + h] * W[h * Cc + c];
    out[g * Cc + c] = acc * inv + b[c];
}

// ---------------- host orchestration ----------------
extern "C" void kernel_launch(void* const* d_in, const int* in_sizes, int n_in,
                              void* d_out, int out_size)
{
    const float* x     = (const float*)d_in[0];
    const int*   ei    = (const int*)d_in[1];
    const int*   batch = (const int*)d_in[2];
    const float* Wq1 = (const float*)d_in[3];
    const float* bq1 = (const float*)d_in[4];
    const float* Wk1 = (const float*)d_in[5];
    const float* bk1 = (const float*)d_in[6];
    const float* Wv1 = (const float*)d_in[7];
    const float* bv1 = (const float*)d_in[8];
    const float* Ws1 = (const float*)d_in[9];
    const float* bs1 = (const float*)d_in[10];
    const float* bn1g = (const float*)d_in[11];
    const float* bn1b = (const float*)d_in[12];
    const float* Wq = (const float*)d_in[13];
    const float* bq = (const float*)d_in[14];
    const float* Wk = (const float*)d_in[15];
    const float* bk = (const float*)d_in[16];
    const float* Wv = (const float*)d_in[17];
    const float* bv = (const float*)d_in[18];
    const float* Ws = (const float*)d_in[19];
    const float* bs = (const float*)d_in[20];
    const float* bng = (const float*)d_in[21];
    const float* bnb = (const float*)d_in[22];
    const float* linW = (const float*)d_in[23];
    const float* linb = (const float*)d_in[24];

    int n = in_sizes[0] / IN_DIM;
    int E = in_sizes[1] / 2;
    int ntiles = (n + 127) / 128;
    const int* src = ei;
    const int* dst = ei + E;
    const int NB = 2048;

    const int SMEM64  = (128 * (IN_DIM + 8)) * 2 + 2 * BTSZ * 2;  // 18432+36864=55296
    const int SMEM128 = (128 * (Hd + 8)) * 2 + 2 * BTSZ * 2;      // 34816+36864=71680
    cudaFuncSetAttribute((const void*)gemm_mma<IN_DIM, false>, cudaFuncAttributeMaxDynamicSharedMemorySize, SMEM64);
    cudaFuncSetAttribute((const void*)gemm_mma<Hd, true>,      cudaFuncAttributeMaxDynamicSharedMemorySize, SMEM128);

    // #1 prep, #2 setup, #3 scan
    prep_layer1<<<1024, 256>>>(x, n, ntiles, Wq1, Wk1, Wv1, Ws1, bq1, bk1, bv1, bs1);
    setup2<<<(E + 255) / 256, 256>>>(dst, batch, n, E);
    scan_block<<<1, 1024>>>(n);
    // #4 GEMM layer 1
    gemm_mma<IN_DIM, false><<<dim3(ntiles, 2), 256, SMEM64>>>(n);
    // #5 scatter
    csr_scatter<<<(E + 255) / 256, 256>>>(src, dst, E);
    // #6 attention layer 1 + BN stats + B prep for hidden layer 0
    attn_fused<<<NB + 256, 256>>>(n, NB, bn1g, bn1b, Wq, Wk, Wv, Ws, bq, bk, bv, bs);

    for (int i = 0; i < Ld; i++) {
        gemm_mma<Hd, true><<<dim3(ntiles, 2), 256, SMEM128>>>(n);
        int last = (i == Ld - 1);
        const float* nWq = last ? nullptr : Wq + (size_t)(i + 1) * Hd * Hd;
        const float* nWk = last ? nullptr : Wk + (size_t)(i + 1) * Hd * Hd;
        const float* nWv = last ? nullptr : Wv + (size_t)(i + 1) * Hd * Hd;
        const float* nWs = last ? nullptr : Ws + (size_t)(i + 1) * Hd * Hd;
        const float* nbq = last ? nullptr : bq + (i + 1) * Hd;
        const float* nbk = last ? nullptr : bk + (i + 1) * Hd;
        const float* nbv = last ? nullptr : bv + (i + 1) * Hd;
        const float* nbs = last ? nullptr : bs + (i + 1) * Hd;
        attn_fused<<<NB + 256, 256>>>(n, NB, bng + i * Hd, bnb + i * Hd,
                                      nWq, nWk, nWv, nWs, nbq, nbk, nbv, nbs);
    }

    bn_pool<<<512, 256>>>(n, batch);
    classify<<<Gg, 32>>>(linW, linb, (float*)d_out);
}